// round 15
// baseline (speedup 1.0000x reference)
#include <cuda_runtime.h>
#include <cuda_bf16.h>
#include <math.h>
#include <stdint.h>

// ---------------- problem constants ----------------
constexpr int cB = 16, cS = 512, cE = 768, cH = 2, cHD = 384;
constexpr int cFF = 256, cL = 3, cENC = 128, cIN = 234;
constexpr int cM = cB * cS;
constexpr float NEGBIG = -1e9f;

// ---------------- fp32 scratch (only what is actually read as fp32) --------
__device__ float g_x  [cM * cE];
__device__ float g_h  [cM * cE];
__device__ float g_sc [cB * cH * cS * cS];

// ---------------- bf16 hi/lo planes (activations) ----------------
__device__ __nv_bfloat16 x_h[cM * cE],      x_l[cM * cE];
__device__ __nv_bfloat16 a_h[cM * cE],      a_l[cM * cE];
__device__ __nv_bfloat16 mem_h[cM * cE],    mem_l[cM * cE];
__device__ __nv_bfloat16 enc_h[cM * cENC],  enc_l[cM * cENC];
__device__ __nv_bfloat16 qkv_h[cM * 3 * cE], qkv_l[cM * 3 * cE];
__device__ __nv_bfloat16 sc_h[cB * cH * cS * cS], sc_l[cB * cH * cS * cS];
__device__ __nv_bfloat16 cakv_h[cL * cM * 2 * cE], cakv_l[cL * cM * 2 * cE];
// ---------------- bf16 hi/lo planes (weights, split once per call) ----------
__device__ __nv_bfloat16 wsai_h[cL * 3 * cE * cE], wsai_l[cL * 3 * cE * cE];
__device__ __nv_bfloat16 wsao_h[cL * cE * cE],     wsao_l[cL * cE * cE];
__device__ __nv_bfloat16 wcai_h[cL * 3 * cE * cE], wcai_l[cL * 3 * cE * cE];
__device__ __nv_bfloat16 wcao_h[cL * cE * cE],     wcao_l[cL * cE * cE];
__device__ __nv_bfloat16 ww1_h[cL * cFF * cE],     ww1_l[cL * cFF * cE];
__device__ __nv_bfloat16 ww2_h[cL * cE * cFF],     ww2_l[cL * cE * cFF];
__device__ __nv_bfloat16 wenc_h[cE * cENC],        wenc_l[cE * cENC];
__device__ __nv_bfloat16 we2d_h[cENC * cE],        we2d_l[cENC * cE];

__device__ __forceinline__ void split1(float v, __nv_bfloat16& h, __nv_bfloat16& l) {
    h = __float2bfloat16_rn(v);
    l = __float2bfloat16_rn(v - __bfloat162float(h));
}

// ============ bf16-plane mma.sync GEMM =================
// C = A * op(B). 128x128 CTA tile, 256 thr, 8 warps (2x4), warp tile 64x32.
// Inputs are pre-split bf16 hi/lo planes; D += Ah*Bh + Ah*Bl + Al*Bh.
// cp.async staging, double-buffered smem, ldmatrix fragment loads.
// fp32 C and hi/lo plane outputs are BOTH optional (nullable).
// CAUSAL blocks entirely above the diagonal early-exit with NEGBIG.
// NOTE: no minBlocksPerMultiprocessor — forcing 2 CTAs/SM (regs<=128) spills
// the hot loop (measured: 9914us vs 6990us). This kernel needs ~170 regs.
// M, N multiples of 128; K multiple of 32.

constexpr int TBK = 32;
// per-buffer smem layout (bytes): Ahi 0 (128 rows x 80B), Alo 10240,
// Bhi 20480, Blo 30720. TN B: 128n x 80B rows. NN B: 32k x 272B rows.
constexpr int SM_BUF = 40960;
constexpr int TSMEM  = 2 * SM_BUF;   // 81920

__device__ __forceinline__ uint32_t smem_u32(const void* p) {
    uint32_t a;
    asm("{ .reg .u64 t; cvta.to.shared.u64 t, %1; cvt.u32.u64 %0, t; }"
        : "=r"(a) : "l"(p));
    return a;
}
__device__ __forceinline__ void cp16(uint32_t s, const void* g) {
    asm volatile("cp.async.ca.shared.global [%0], [%1], 16;"
                 :: "r"(s), "l"(g) : "memory");
}
__device__ __forceinline__ void ldsm4(uint32_t* r, uint32_t a) {
    asm volatile("ldmatrix.sync.aligned.m8n8.x4.shared.b16 {%0,%1,%2,%3}, [%4];"
        : "=r"(r[0]), "=r"(r[1]), "=r"(r[2]), "=r"(r[3]) : "r"(a));
}
__device__ __forceinline__ void ldsm4t(uint32_t* r, uint32_t a) {
    asm volatile("ldmatrix.sync.aligned.m8n8.x4.trans.shared.b16 {%0,%1,%2,%3}, [%4];"
        : "=r"(r[0]), "=r"(r[1]), "=r"(r[2]), "=r"(r[3]) : "r"(a));
}
__device__ __forceinline__ void mma16(float* d, const uint32_t* a, const uint32_t* b) {
    asm volatile(
        "mma.sync.aligned.m16n8k16.row.col.f32.bf16.bf16.f32 "
        "{%0,%1,%2,%3}, {%4,%5,%6,%7}, {%8,%9}, {%0,%1,%2,%3};"
        : "+f"(d[0]), "+f"(d[1]), "+f"(d[2]), "+f"(d[3])
        : "r"(a[0]), "r"(a[1]), "r"(a[2]), "r"(a[3]), "r"(b[0]), "r"(b[1]));
}

template<bool TRANSB>
__device__ __forceinline__ void stage(
    const __nv_bfloat16* __restrict__ Ah, const __nv_bfloat16* __restrict__ Al, int lda,
    const __nv_bfloat16* __restrict__ Bh, const __nv_bfloat16* __restrict__ Bl, int ldb,
    int row0, int col0, int k0, uint32_t sbuf, int tid)
{
    #pragma unroll
    for (int i = 0; i < 2; i++) {
        int s = tid + i * 256;
        int r = s >> 2, kq = s & 3;
        uint32_t off = (uint32_t)(r * 80 + kq * 16);
        size_t gidx = (size_t)(row0 + r) * lda + k0 + kq * 8;
        cp16(sbuf + off,         Ah + gidx);
        cp16(sbuf + 10240 + off, Al + gidx);
    }
    if (TRANSB) {
        #pragma unroll
        for (int i = 0; i < 2; i++) {
            int s = tid + i * 256;
            int n = s >> 2, kq = s & 3;
            uint32_t off = (uint32_t)(n * 80 + kq * 16);
            size_t gidx = (size_t)(col0 + n) * ldb + k0 + kq * 8;
            cp16(sbuf + 20480 + off, Bh + gidx);
            cp16(sbuf + 30720 + off, Bl + gidx);
        }
    } else {
        #pragma unroll
        for (int i = 0; i < 2; i++) {
            int s = tid + i * 256;
            int k = s >> 4, ns = s & 15;
            uint32_t off = (uint32_t)(k * 272 + ns * 16);
            size_t gidx = (size_t)(k0 + k) * ldb + col0 + ns * 8;
            cp16(sbuf + 20480 + off, Bh + gidx);
            cp16(sbuf + 30720 + off, Bl + gidx);
        }
    }
    asm volatile("cp.async.commit_group;" ::: "memory");
}

template<bool TRANSB, bool RELU, bool CAUSAL>
__global__ void __launch_bounds__(256)
tmma_k(int K,
       const __nv_bfloat16* __restrict__ Ah, const __nv_bfloat16* __restrict__ Al,
       int lda, long long sAo, long long sAi,
       const __nv_bfloat16* __restrict__ Bh, const __nv_bfloat16* __restrict__ Bl,
       int ldb, long long sBo, long long sBi,
       float* __restrict__ C, __nv_bfloat16* __restrict__ Chi,
       __nv_bfloat16* __restrict__ Clo,
       int ldc, long long sCo, long long sCi,
       const float* __restrict__ bias, float scale, int innerH)
{
    extern __shared__ char smraw[];
    int z  = blockIdx.z;
    int zo = z / innerH, zi = z - zo * innerH;
    Ah += zo * sAo + zi * sAi;  Al += zo * sAo + zi * sAi;
    Bh += zo * sBo + zi * sBi;  Bl += zo * sBo + zi * sBi;
    if (C) C += zo * sCo + zi * sCi;
    if (Chi) { Chi += zo * sCo + zi * sCi; Clo += zo * sCo + zi * sCi; }

    const int tid = threadIdx.x;
    const int lane = tid & 31;
    const int wid  = tid >> 5;
    const int wm = wid >> 2, wn = wid & 3;
    const int row0 = blockIdx.y * 128;
    const int col0 = blockIdx.x * 128;
    const int lr = lane >> 2, lc = lane & 3;
    const int g = lane >> 3, li = lane & 7;

    // fully-masked causal block: skip all compute, emit NEGBIG
    if (CAUSAL && col0 > row0 + 127) {
        #pragma unroll
        for (int mt = 0; mt < 4; mt++) {
            int rb = row0 + wm * 64 + mt * 16 + lr;
            #pragma unroll
            for (int nt = 0; nt < 4; nt++) {
                int cc = col0 + wn * 32 + nt * 8 + 2 * lc;
                #pragma unroll
                for (int half = 0; half < 2; half++) {
                    size_t o = (size_t)(rb + half * 8) * ldc + cc;
                    *(float2*)&C[o] = make_float2(NEGBIG, NEGBIG);
                }
            }
        }
        return;
    }

    const uint32_t sb = smem_u32(smraw);

    // per-lane ldmatrix offsets
    const uint32_t aoff = (uint32_t)((wm * 64 + (g & 1) * 8 + li) * 80 + (g >> 1) * 16);
    uint32_t boff[2];
    #pragma unroll
    for (int p2 = 0; p2 < 2; p2++) {
        if (TRANSB)
            boff[p2] = (uint32_t)((wn * 32 + p2 * 16 + (g >> 1) * 8 + li) * 80 + (g & 1) * 16);
        else
            boff[p2] = (uint32_t)(((g & 1) * 8 + li) * 272 + (wn * 32 + (2 * p2 + (g >> 1)) * 8) * 2);
    }

    float acc[4][4][4];
    #pragma unroll
    for (int i = 0; i < 4; i++)
        #pragma unroll
        for (int j = 0; j < 4; j++)
            #pragma unroll
            for (int q = 0; q < 4; q++) acc[i][j][q] = 0.f;

    const int nch = K / TBK;
    stage<TRANSB>(Ah, Al, lda, Bh, Bl, ldb, row0, col0, 0, sb, tid);

    for (int c = 0; c < nch; c++) {
        int buf = c & 1;
        uint32_t sbuf = sb + buf * SM_BUF;
        if (c + 1 < nch) {
            stage<TRANSB>(Ah, Al, lda, Bh, Bl, ldb, row0, col0,
                          (c + 1) * TBK, sb + (buf ^ 1) * SM_BUF, tid);
            asm volatile("cp.async.wait_group 1;" ::: "memory");
        } else {
            asm volatile("cp.async.wait_group 0;" ::: "memory");
        }
        __syncthreads();

        #pragma unroll
        for (int ks = 0; ks < 2; ks++) {
            uint32_t bh[2][4], bl[2][4];
            #pragma unroll
            for (int p2 = 0; p2 < 2; p2++) {
                uint32_t ba = sbuf + 20480 + boff[p2] +
                              (TRANSB ? (uint32_t)(ks * 32) : (uint32_t)(ks * 16 * 272));
                if (TRANSB) { ldsm4(bh[p2], ba); ldsm4(bl[p2], ba + 10240); }
                else        { ldsm4t(bh[p2], ba); ldsm4t(bl[p2], ba + 10240); }
            }
            #pragma unroll
            for (int mt = 0; mt < 4; mt++) {
                uint32_t aa = sbuf + aoff + (uint32_t)(mt * 16 * 80 + ks * 32);
                uint32_t ah[4], al[4];
                ldsm4(ah, aa);
                ldsm4(al, aa + 10240);
                #pragma unroll
                for (int nt = 0; nt < 4; nt++) {
                    const uint32_t* bhp = &bh[nt >> 1][(nt & 1) * 2];
                    const uint32_t* blp = &bl[nt >> 1][(nt & 1) * 2];
                    mma16(acc[mt][nt], ah, bhp);
                    mma16(acc[mt][nt], ah, blp);
                    mma16(acc[mt][nt], al, bhp);
                }
            }
        }
        __syncthreads();
    }

    // ---- epilogue: optional fp32 C and optional hi/lo plane split ----
    #pragma unroll
    for (int mt = 0; mt < 4; mt++) {
        int rb = row0 + wm * 64 + mt * 16 + lr;
        #pragma unroll
        for (int nt = 0; nt < 4; nt++) {
            int cc = col0 + wn * 32 + nt * 8 + 2 * lc;
            #pragma unroll
            for (int half = 0; half < 2; half++) {
                int r = rb + half * 8;
                float v0 = acc[mt][nt][half * 2 + 0] * scale;
                float v1 = acc[mt][nt][half * 2 + 1] * scale;
                if (CAUSAL) {
                    if (cc > r)     v0 += NEGBIG;
                    if (cc + 1 > r) v1 += NEGBIG;
                }
                if (bias) { v0 += bias[cc]; v1 += bias[cc + 1]; }
                if (RELU) { v0 = fmaxf(v0, 0.f); v1 = fmaxf(v1, 0.f); }
                size_t o = (size_t)r * ldc + cc;
                if (C) *(float2*)&C[o] = make_float2(v0, v1);
                if (Chi) {
                    __nv_bfloat16 h0, l0, h1, l1;
                    split1(v0, h0, l0); split1(v1, h1, l1);
                    *(__nv_bfloat162*)&Chi[o] = __halves2bfloat162(h0, h1);
                    *(__nv_bfloat162*)&Clo[o] = __halves2bfloat162(l0, l1);
                }
            }
        }
    }
}

// ================= SIMT GEMM (prenet only: K=234) =============
#define BM 128
#define BN 128
#define BKT 16

__global__ void __launch_bounds__(256)
gemm_nn_k(int M, int N, int K,
          const float* __restrict__ A, int lda,
          const float* __restrict__ B, int ldb,
          __nv_bfloat16* __restrict__ Chi, __nv_bfloat16* __restrict__ Clo,
          int ldc, const float* __restrict__ bias)
{
    __shared__ __align__(16) float As[BKT][BM];
    __shared__ __align__(16) float Bs[BKT][BN];

    int tid = threadIdx.x;
    int tx = tid & 15, ty = tid >> 4;
    int row0 = blockIdx.y * BM, col0 = blockIdx.x * BN;

    float acc[8][8];
    #pragma unroll
    for (int i = 0; i < 8; i++)
        #pragma unroll
        for (int j = 0; j < 8; j++) acc[i][j] = 0.f;

    for (int k0 = 0; k0 < K; k0 += BKT) {
        #pragma unroll
        for (int t = 0; t < 2; t++) {
            int slot = tid + t * 256;
            int r = slot >> 2, cq = slot & 3;
            const float* ap = A + (size_t)(row0 + r) * lda + k0 + cq * 4;
            #pragma unroll
            for (int j = 0; j < 4; j++) {
                int gk = k0 + cq * 4 + j;
                As[cq * 4 + j][r] = (gk < K) ? ap[j] : 0.f;
            }
        }
        #pragma unroll
        for (int t = 0; t < 2; t++) {
            int slot = tid + t * 256;
            int kk = slot >> 5, n4 = slot & 31;
            int gk = k0 + kk;
            const float* bp = B + (size_t)gk * ldb + col0 + n4 * 4;
            #pragma unroll
            for (int j = 0; j < 4; j++)
                Bs[kk][n4 * 4 + j] = (gk < K) ? bp[j] : 0.f;
        }
        __syncthreads();

        #pragma unroll
        for (int kk = 0; kk < BKT; kk++) {
            float4 a0 = *(const float4*)&As[kk][ty * 4];
            float4 a1 = *(const float4*)&As[kk][64 + ty * 4];
            float4 b0 = *(const float4*)&Bs[kk][tx * 4];
            float4 b1 = *(const float4*)&Bs[kk][64 + tx * 4];
            float av[8] = {a0.x, a0.y, a0.z, a0.w, a1.x, a1.y, a1.z, a1.w};
            float bv[8] = {b0.x, b0.y, b0.z, b0.w, b1.x, b1.y, b1.z, b1.w};
            #pragma unroll
            for (int i = 0; i < 8; i++)
                #pragma unroll
                for (int j = 0; j < 8; j++)
                    acc[i][j] += av[i] * bv[j];
        }
        __syncthreads();
    }

    #pragma unroll
    for (int i = 0; i < 8; i++) {
        int r = row0 + ((i < 4) ? (ty * 4 + i) : (64 + ty * 4 + i - 4));
        #pragma unroll
        for (int jb = 0; jb < 2; jb++) {
            int c0 = col0 + jb * 64 + tx * 4;
            size_t o = (size_t)r * ldc + c0;
            #pragma unroll
            for (int j = 0; j < 4; j++) {
                float v = acc[i][jb * 4 + j] + bias[c0 + j];
                __nv_bfloat16 hh, ll;
                split1(v, hh, ll);
                Chi[o + j] = hh; Clo[o + j] = ll;
            }
        }
    }
}

// ---------------- split kernels ----------------
__global__ void split_k(const float* __restrict__ src,
                        __nv_bfloat16* __restrict__ hi,
                        __nv_bfloat16* __restrict__ lo, int n)
{
    int i = blockIdx.x * blockDim.x + threadIdx.x;
    if (i >= n) return;
    split1(src[i], hi[i], lo[i]);
}

__global__ void copy_split_k(float* __restrict__ dst, const float* __restrict__ src,
                             __nv_bfloat16* __restrict__ hi,
                             __nv_bfloat16* __restrict__ lo, int n)
{
    int i = blockIdx.x * blockDim.x + threadIdx.x;
    if (i >= n) return;
    float v = src[i];
    dst[i] = v;
    split1(v, hi[i], lo[i]);
}

// ---------------- block reduce ----------------
__device__ __forceinline__ float blockReduceSum(float v, float* s) {
    int tid = threadIdx.x;
    int nw = blockDim.x >> 5;
    #pragma unroll
    for (int o = 16; o; o >>= 1) v += __shfl_xor_sync(0xffffffffu, v, o);
    if ((tid & 31) == 0) s[tid >> 5] = v;
    __syncthreads();
    if (tid < 32) {
        float t = (tid < nw) ? s[tid] : 0.f;
        #pragma unroll
        for (int o = 16; o; o >>= 1) t += __shfl_xor_sync(0xffffffffu, t, o);
        if (tid == 0) s[0] = t;
    }
    __syncthreads();
    float r = s[0];
    __syncthreads();
    return r;
}

// ---------------- register-resident softmax for 512 cols ----------------
// reads fp32 scores, writes ONLY the hi/lo planes (no fp32 round-trip).
__global__ void softmax512_k(const float* __restrict__ x,
                             __nv_bfloat16* __restrict__ hi,
                             __nv_bfloat16* __restrict__ lo)
{
    size_t base = (size_t)blockIdx.x * 512;
    int tid = threadIdx.x;
    __shared__ float red[32];

    float v0 = x[base + tid];
    float v1 = x[base + tid + 256];

    float mx = fmaxf(v0, v1);
    #pragma unroll
    for (int o = 16; o; o >>= 1) mx = fmaxf(mx, __shfl_xor_sync(0xffffffffu, mx, o));
    if ((tid & 31) == 0) red[tid >> 5] = mx;
    __syncthreads();
    if (tid < 32) {
        float t = (tid < 8) ? red[tid] : -3.4e38f;
        #pragma unroll
        for (int o = 16; o; o >>= 1) t = fmaxf(t, __shfl_xor_sync(0xffffffffu, t, o));
        if (tid == 0) red[0] = t;
    }
    __syncthreads();
    mx = red[0];
    __syncthreads();

    float e0 = expf(v0 - mx);
    float e1 = expf(v1 - mx);
    float sum = blockReduceSum(e0 + e1, red);
    float inv = 1.f / sum;

    __nv_bfloat16 hh, ll;
    split1(e0 * inv, hh, ll);
    hi[base + tid] = hh; lo[base + tid] = ll;
    split1(e1 * inv, hh, ll);
    hi[base + tid + 256] = hh; lo[base + tid + 256] = ll;
}

// ---------------- fused x = LayerNorm(x + h) (+ split planes) ---------------
__global__ void add_ln_k(float* __restrict__ x, const float* __restrict__ h,
                         __nv_bfloat16* __restrict__ hi, __nv_bfloat16* __restrict__ lo,
                         const float* __restrict__ g, const float* __restrict__ b,
                         int ncols)
{
    size_t base = (size_t)blockIdx.x * ncols;
    int tid = threadIdx.x;
    __shared__ float red[32];

    float v[4];
    float sum = 0.f;
    int c = 0;
    for (int i = tid; i < ncols; i += blockDim.x, c++) {
        v[c] = x[base + i] + h[base + i];
        sum += v[c];
    }
    sum = blockReduceSum(sum, red);
    float mu = sum / ncols;

    float sq = 0.f;
    c = 0;
    for (int i = tid; i < ncols; i += blockDim.x, c++) {
        float d = v[c] - mu;
        sq += d * d;
    }
    sq = blockReduceSum(sq, red);
    float rstd = rsqrtf(sq / ncols + 1e-5f);

    c = 0;
    for (int i = tid; i < ncols; i += blockDim.x, c++) {
        float o = (v[c] - mu) * rstd * g[i] + b[i];
        x[base + i] = o;
        split1(o, hi[base + i], lo[base + i]);
    }
}

// ---------------- scheduled sampling mix (+ split planes) ----------------
__global__ void mix_k(float* __restrict__ x, const float* __restrict__ labels,
                      __nv_bfloat16* __restrict__ hi, __nv_bfloat16* __restrict__ lo,
                      const float* __restrict__ sr, const int* __restrict__ steps,
                      int total)
{
    int i = blockIdx.x * blockDim.x + threadIdx.x;
    if (i >= total) return;
    int s = (i / cE) % cS;
    int b = i / (cE * cS);
    float thr = (float)(*steps) / 200000.0f;
    float v = (sr[s * cB + b] >= thr) ? labels[i] : x[i];
    x[i] = v;
    split1(v, hi[i], lo[i]);
}

// ---------------- host dispatch ----------------
struct Planes { const __nv_bfloat16 *h, *l; };

static void launch_tmma(bool transB, bool relu, bool causal,
                        int M, int N, int K,
                        Planes A, int lda, long long sAo, long long sAi,
                        Planes B, int ldb, long long sBo, long long sBi,
                        float* C, __nv_bfloat16* Chi, __nv_bfloat16* Clo,
                        int ldc, long long sCo, long long sCi,
                        const float* bias, float scale, int nz, int innerH)
{
    dim3 blk(256);
    dim3 grd(N / 128, M / 128, nz);
    if (!transB) {
        cudaFuncSetAttribute((const void*)tmma_k<false, false, false>,
                             cudaFuncAttributeMaxDynamicSharedMemorySize, TSMEM);
        tmma_k<false, false, false><<<grd, blk, TSMEM>>>(K, A.h, A.l, lda, sAo, sAi,
            B.h, B.l, ldb, sBo, sBi, C, Chi, Clo, ldc, sCo, sCi, bias, scale, innerH);
    } else if (causal) {
        cudaFuncSetAttribute((const void*)tmma_k<true, false, true>,
                             cudaFuncAttributeMaxDynamicSharedMemorySize, TSMEM);
        tmma_k<true, false, true><<<grd, blk, TSMEM>>>(K, A.h, A.l, lda, sAo, sAi,
            B.h, B.l, ldb, sBo, sBi, C, Chi, Clo, ldc, sCo, sCi, bias, scale, innerH);
    } else if (relu) {
        cudaFuncSetAttribute((const void*)tmma_k<true, true, false>,
                             cudaFuncAttributeMaxDynamicSharedMemorySize, TSMEM);
        tmma_k<true, true, false><<<grd, blk, TSMEM>>>(K, A.h, A.l, lda, sAo, sAi,
            B.h, B.l, ldb, sBo, sBi, C, Chi, Clo, ldc, sCo, sCi, bias, scale, innerH);
    } else {
        cudaFuncSetAttribute((const void*)tmma_k<true, false, false>,
                             cudaFuncAttributeMaxDynamicSharedMemorySize, TSMEM);
        tmma_k<true, false, false><<<grd, blk, TSMEM>>>(K, A.h, A.l, lda, sAo, sAi,
            B.h, B.l, ldb, sBo, sBi, C, Chi, Clo, ldc, sCo, sCi, bias, scale, innerH);
    }
}

template<typename T>
static T* sym(T* symbol) {
    void* p = nullptr;
    cudaGetSymbolAddress(&p, (const void*)symbol);
    return (T*)p;
}

extern "C" void kernel_launch(void* const* d_in, const int* in_sizes, int n_in,
                              void* d_out, int out_size)
{
    const float* batch    = (const float*)d_in[0];
    const float* labels   = (const float*)d_in[1];
    const float* sched    = (const float*)d_in[2];
    const int*   steps    = (const int*)  d_in[3];
    const float* W_pre    = (const float*)d_in[4];
    const float* b_pre    = (const float*)d_in[5];
    const float* W_enc    = (const float*)d_in[6];
    const float* b_enc    = (const float*)d_in[7];
    const float* W_e2d    = (const float*)d_in[8];
    const float* b_e2d    = (const float*)d_in[9];
    const float* sa_in_w  = (const float*)d_in[10];
    const float* sa_in_b  = (const float*)d_in[11];
    const float* sa_out_w = (const float*)d_in[12];
    const float* sa_out_b = (const float*)d_in[13];
    const float* ca_in_w  = (const float*)d_in[14];
    const float* ca_in_b  = (const float*)d_in[15];
    const float* ca_out_w = (const float*)d_in[16];
    const float* ca_out_b = (const float*)d_in[17];
    const float* w1       = (const float*)d_in[18];
    const float* b1       = (const float*)d_in[19];
    const float* w2       = (const float*)d_in[20];
    const float* b2       = (const float*)d_in[21];
    const float* g1       = (const float*)d_in[22];
    const float* be1      = (const float*)d_in[23];
    const float* g2       = (const float*)d_in[24];
    const float* be2      = (const float*)d_in[25];
    const float* g3       = (const float*)d_in[26];
    const float* be3      = (const float*)d_in[27];

    float* x  = sym(g_x);
    float* h  = sym(g_h);
    float* sc = sym(g_sc);

    __nv_bfloat16 *xh = sym(x_h), *xl = sym(x_l);
    __nv_bfloat16 *ah = sym(a_h), *al = sym(a_l);
    __nv_bfloat16 *memh = sym(mem_h), *meml = sym(mem_l);
    __nv_bfloat16 *ench = sym(enc_h), *encl = sym(enc_l);
    __nv_bfloat16 *qkvh = sym(qkv_h), *qkvl = sym(qkv_l);
    __nv_bfloat16 *sch = sym(sc_h), *scl = sym(sc_l);
    __nv_bfloat16 *cakvh = sym(cakv_h), *cakvl = sym(cakv_l);
    __nv_bfloat16 *wsaih = sym(wsai_h), *wsail = sym(wsai_l);
    __nv_bfloat16 *wsaoh = sym(wsao_h), *wsaol = sym(wsao_l);
    __nv_bfloat16 *wcaih = sym(wcai_h), *wcail = sym(wcai_l);
    __nv_bfloat16 *wcaoh = sym(wcao_h), *wcaol = sym(wcao_l);
    __nv_bfloat16 *ww1h = sym(ww1_h), *ww1l = sym(ww1_l);
    __nv_bfloat16 *ww2h = sym(ww2_h), *ww2l = sym(ww2_l);
    __nv_bfloat16 *wench = sym(wenc_h), *wencl = sym(wenc_l);
    __nv_bfloat16 *we2dh = sym(we2d_h), *we2dl = sym(we2d_l);

    const float atscale = 1.0f / sqrtf((float)cHD);
    const long long sQb  = (long long)cS * 3 * cE;
    const long long sKVb = (long long)cS * 2 * cE;
    const long long sScb = (long long)cH * cS * cS;
    const long long sSch = (long long)cS * cS;
    const long long sAb  = (long long)cS * cE;

    // ---- weight splits (once per call) ----
    auto spl = [](const float* s, __nv_bfloat16* hh, __nv_bfloat16* ll, int n) {
        split_k<<<(n + 255) / 256, 256>>>(s, hh, ll, n);
    };
    spl(sa_in_w,  wsaih, wsail, cL * 3 * cE * cE);
    spl(sa_out_w, wsaoh, wsaol, cL * cE * cE);
    spl(ca_in_w,  wcaih, wcail, cL * 3 * cE * cE);
    spl(ca_out_w, wcaoh, wcaol, cL * cE * cE);
    spl(w1, ww1h, ww1l, cL * cFF * cE);
    spl(w2, ww2h, ww2l, cL * cE * cFF);
    spl(W_enc, wench, wencl, cE * cENC);
    spl(W_e2d, we2dh, we2dl, cENC * cE);

    // ---- prenet (SIMT, K=234, planes only) + encoder chain (NN tensor) ----
    {
        dim3 blk(256), grd(cE / BN, cM / BM, 1);
        gemm_nn_k<<<grd, blk>>>(cM, cE, cIN, batch, cIN, W_pre, cE,
                                ah, al, cE, b_pre);
    }
    launch_tmma(false, false, false, cM, cENC, cE,
                {ah, al}, cE, 0, 0, {wench, wencl}, cENC, 0, 0,
                nullptr, ench, encl, cENC, 0, 0, b_enc, 1.f, 1, 1);
    launch_tmma(false, false, false, cM, cE, cENC,
                {ench, encl}, cENC, 0, 0, {we2dh, we2dl}, cE, 0, 0,
                nullptr, memh, meml, cE, 0, 0, b_e2d, 1.f, 1, 1);

    {
        int total = cM * cE;
        copy_split_k<<<(total + 255) / 256, 256>>>(x, labels, xh, xl, total);
    }

    for (int p = 0; p < 2; p++) {
        for (int l = 0; l < cL; l++) {
            size_t wqkvOff = (size_t)l * 3 * cE * cE;
            size_t woOff   = (size_t)l * cE * cE;
            const float* sib = sa_in_b + (size_t)l * 3 * cE;
            const float* cib = ca_in_b + (size_t)l * 3 * cE;
            size_t kvOff = (size_t)l * cM * 2 * cE;

            // ===== self-attention =====
            launch_tmma(true, false, false, cM, 3 * cE, cE,
                        {xh, xl}, cE, 0, 0,
                        {wsaih + wqkvOff, wsail + wqkvOff}, cE, 0, 0,
                        nullptr, qkvh, qkvl, 3 * cE, 0, 0, sib, 1.f, 1, 1);
            launch_tmma(true, false, true, cS, cS, cHD,
                        {qkvh, qkvl}, 3 * cE, sQb, cHD,
                        {qkvh + cE, qkvl + cE}, 3 * cE, sQb, cHD,
                        sc, nullptr, nullptr, cS, sScb, sSch, nullptr, atscale,
                        cB * cH, cH);
            softmax512_k<<<cB * cH * cS, 256>>>(sc, sch, scl);
            launch_tmma(false, false, false, cS, cHD, cS,
                        {sch, scl}, cS, sScb, sSch,
                        {qkvh + 2 * cE, qkvl + 2 * cE}, 3 * cE, sQb, cHD,
                        nullptr, ah, al, cE, sAb, cHD, nullptr, 1.f, cB * cH, cH);
            launch_tmma(true, false, false, cM, cE, cE,
                        {ah, al}, cE, 0, 0,
                        {wsaoh + woOff, wsaol + woOff}, cE, 0, 0,
                        h, nullptr, nullptr, cE, 0, 0,
                        sa_out_b + (size_t)l * cE, 1.f, 1, 1);
            add_ln_k<<<cM, 256>>>(x, h, xh, xl,
                                  g1 + (size_t)l * cE, be1 + (size_t)l * cE, cE);

            // ===== cross-attention (K/V cached across passes) =====
            launch_tmma(true, false, false, cM, cE, cE,
                        {xh, xl}, cE, 0, 0,
                        {wcaih + wqkvOff, wcail + wqkvOff}, cE, 0, 0,
                        nullptr, qkvh, qkvl, 3 * cE, 0, 0, cib, 1.f, 1, 1);
            if (p == 0)
                launch_tmma(true, false, false, cM, 2 * cE, cE,
                            {memh, meml}, cE, 0, 0,
                            {wcaih + wqkvOff + (size_t)cE * cE,
                             wcail + wqkvOff + (size_t)cE * cE}, cE, 0, 0,
                            nullptr, cakvh + kvOff, cakvl + kvOff,
                            2 * cE, 0, 0, cib + cE, 1.f, 1, 1);
            launch_tmma(true, false, false, cS, cS, cHD,
                        {qkvh, qkvl}, 3 * cE, sQb, cHD,
                        {cakvh + kvOff, cakvl + kvOff}, 2 * cE, sKVb, cHD,
                        sc, nullptr, nullptr, cS, sScb, sSch, nullptr, atscale,
                        cB * cH, cH);
            softmax512_k<<<cB * cH * cS, 256>>>(sc, sch, scl);
            launch_tmma(false, false, false, cS, cHD, cS,
                        {sch, scl}, cS, sScb, sSch,
                        {cakvh + kvOff + cE, cakvl + kvOff + cE}, 2 * cE, sKVb, cHD,
                        nullptr, ah, al, cE, sAb, cHD, nullptr, 1.f, cB * cH, cH);
            launch_tmma(true, false, false, cM, cE, cE,
                        {ah, al}, cE, 0, 0,
                        {wcaoh + woOff, wcaol + woOff}, cE, 0, 0,
                        h, nullptr, nullptr, cE, 0, 0,
                        ca_out_b + (size_t)l * cE, 1.f, 1, 1);
            add_ln_k<<<cM, 256>>>(x, h, xh, xl,
                                  g2 + (size_t)l * cE, be2 + (size_t)l * cE, cE);

            // ===== FFN (relu) — hidden planes reuse qkv plane buffers =====
            launch_tmma(true, true, false, cM, cFF, cE,
                        {xh, xl}, cE, 0, 0,
                        {ww1h + (size_t)l * cFF * cE, ww1l + (size_t)l * cFF * cE},
                        cE, 0, 0,
                        nullptr, qkvh, qkvl, cFF, 0, 0, b1 + (size_t)l * cFF, 1.f, 1, 1);
            launch_tmma(true, false, false, cM, cE, cFF,
                        {qkvh, qkvl}, cFF, 0, 0,
                        {ww2h + (size_t)l * cE * cFF, ww2l + (size_t)l * cE * cFF},
                        cFF, 0, 0,
                        h, nullptr, nullptr, cE, 0, 0, b2 + (size_t)l * cE, 1.f, 1, 1);
            add_ln_k<<<cM, 256>>>(x, h, xh, xl,
                                  g3 + (size_t)l * cE, be3 + (size_t)l * cE, cE);
        }
        if (p == 0) {
            int total = cM * cE;
            mix_k<<<(total + 255) / 256, 256>>>(x, labels, xh, xl, sched, steps, total);
        }
    }

    cudaMemcpyAsync(d_out, x, sizeof(float) * (size_t)cM * cE,
                    cudaMemcpyDeviceToDevice);
}

// round 16
// speedup vs baseline: 1.5659x; 1.5659x over previous
#include <cuda_runtime.h>
#include <cuda_bf16.h>
#include <math.h>
#include <stdint.h>

// ---------------- problem constants ----------------
constexpr int cB = 16, cS = 512, cE = 768, cH = 2, cHD = 384;
constexpr int cFF = 256, cL = 3, cENC = 128, cIN = 234;
constexpr int cM = cB * cS;
constexpr float NEGBIG = -1e9f;

// ---------------- fp32 scratch (only what is actually read as fp32) --------
__device__ float g_x  [cM * cE];
__device__ float g_h  [cM * cE];
__device__ float g_sc [cB * cH * cS * cS];

// ---------------- bf16 hi/lo planes (activations) ----------------
__device__ __nv_bfloat16 x_h[cM * cE],      x_l[cM * cE];
__device__ __nv_bfloat16 a_h[cM * cE],      a_l[cM * cE];
__device__ __nv_bfloat16 mem_h[cM * cE],    mem_l[cM * cE];
__device__ __nv_bfloat16 enc_h[cM * cENC],  enc_l[cM * cENC];
__device__ __nv_bfloat16 qkv_h[cM * 3 * cE], qkv_l[cM * 3 * cE];
__device__ __nv_bfloat16 sc_h[cB * cH * cS * cS], sc_l[cB * cH * cS * cS];
__device__ __nv_bfloat16 cakv_h[cL * cM * 2 * cE], cakv_l[cL * cM * 2 * cE];
// ---------------- bf16 hi/lo planes (weights, split once per call) ----------
__device__ __nv_bfloat16 wsai_h[cL * 3 * cE * cE], wsai_l[cL * 3 * cE * cE];
__device__ __nv_bfloat16 wsao_h[cL * cE * cE],     wsao_l[cL * cE * cE];
__device__ __nv_bfloat16 wcai_h[cL * 3 * cE * cE], wcai_l[cL * 3 * cE * cE];
__device__ __nv_bfloat16 wcao_h[cL * cE * cE],     wcao_l[cL * cE * cE];
__device__ __nv_bfloat16 ww1_h[cL * cFF * cE],     ww1_l[cL * cFF * cE];
__device__ __nv_bfloat16 ww2_h[cL * cE * cFF],     ww2_l[cL * cE * cFF];
__device__ __nv_bfloat16 wenc_h[cE * cENC],        wenc_l[cE * cENC];
__device__ __nv_bfloat16 we2d_h[cENC * cE],        we2d_l[cENC * cE];

__device__ __forceinline__ void split1(float v, __nv_bfloat16& h, __nv_bfloat16& l) {
    h = __float2bfloat16_rn(v);
    l = __float2bfloat16_rn(v - __bfloat162float(h));
}

// ============ bf16-plane mma.sync GEMM =================
// C = A * op(B). 128x128 CTA tile, 256 thr, 8 warps (2x4), warp tile 64x32.
// Inputs are pre-split bf16 hi/lo planes; D += Ah*Bh + Ah*Bl + Al*Bh.
// 3-stage cp.async pipeline, ONE __syncthreads per chunk:
//   [wait_group 1 -> barrier -> issue stage c+2 -> compute c]
// The barrier-before-issue makes buffer reuse safe (iter c+1 writes the
// buffer computed at iter c; barrier guarantees all warps left it).
// fp32 C and hi/lo plane outputs are BOTH optional (nullable).
// CAUSAL blocks entirely above the diagonal early-exit with NEGBIG.
// NOTE: no minBlocksPerMultiprocessor — forcing 2 CTAs/SM (regs<=128) spills.
// M, N multiples of 128; K multiple of 32 (and K/32 >= 2).

constexpr int TBK = 32;
// per-buffer smem layout (bytes): Ahi 0 (128 rows x 80B), Alo 10240,
// Bhi 20480, Blo 30720. TN B: 128n x 80B rows. NN B: 32k x 272B rows.
constexpr int SM_BUF = 40960;
constexpr int NSTAGE = 3;
constexpr int TSMEM  = NSTAGE * SM_BUF;   // 122880 (1 CTA/SM)

__device__ __forceinline__ uint32_t smem_u32(const void* p) {
    uint32_t a;
    asm("{ .reg .u64 t; cvta.to.shared.u64 t, %1; cvt.u32.u64 %0, t; }"
        : "=r"(a) : "l"(p));
    return a;
}
__device__ __forceinline__ void cp16(uint32_t s, const void* g) {
    asm volatile("cp.async.ca.shared.global [%0], [%1], 16;"
                 :: "r"(s), "l"(g) : "memory");
}
__device__ __forceinline__ void ldsm4(uint32_t* r, uint32_t a) {
    asm volatile("ldmatrix.sync.aligned.m8n8.x4.shared.b16 {%0,%1,%2,%3}, [%4];"
        : "=r"(r[0]), "=r"(r[1]), "=r"(r[2]), "=r"(r[3]) : "r"(a));
}
__device__ __forceinline__ void ldsm4t(uint32_t* r, uint32_t a) {
    asm volatile("ldmatrix.sync.aligned.m8n8.x4.trans.shared.b16 {%0,%1,%2,%3}, [%4];"
        : "=r"(r[0]), "=r"(r[1]), "=r"(r[2]), "=r"(r[3]) : "r"(a));
}
__device__ __forceinline__ void mma16(float* d, const uint32_t* a, const uint32_t* b) {
    asm volatile(
        "mma.sync.aligned.m16n8k16.row.col.f32.bf16.bf16.f32 "
        "{%0,%1,%2,%3}, {%4,%5,%6,%7}, {%8,%9}, {%0,%1,%2,%3};"
        : "+f"(d[0]), "+f"(d[1]), "+f"(d[2]), "+f"(d[3])
        : "r"(a[0]), "r"(a[1]), "r"(a[2]), "r"(a[3]), "r"(b[0]), "r"(b[1]));
}

template<bool TRANSB>
__device__ __forceinline__ void stage(
    const __nv_bfloat16* __restrict__ Ah, const __nv_bfloat16* __restrict__ Al, int lda,
    const __nv_bfloat16* __restrict__ Bh, const __nv_bfloat16* __restrict__ Bl, int ldb,
    int row0, int col0, int k0, uint32_t sbuf, int tid)
{
    #pragma unroll
    for (int i = 0; i < 2; i++) {
        int s = tid + i * 256;
        int r = s >> 2, kq = s & 3;
        uint32_t off = (uint32_t)(r * 80 + kq * 16);
        size_t gidx = (size_t)(row0 + r) * lda + k0 + kq * 8;
        cp16(sbuf + off,         Ah + gidx);
        cp16(sbuf + 10240 + off, Al + gidx);
    }
    if (TRANSB) {
        #pragma unroll
        for (int i = 0; i < 2; i++) {
            int s = tid + i * 256;
            int n = s >> 2, kq = s & 3;
            uint32_t off = (uint32_t)(n * 80 + kq * 16);
            size_t gidx = (size_t)(col0 + n) * ldb + k0 + kq * 8;
            cp16(sbuf + 20480 + off, Bh + gidx);
            cp16(sbuf + 30720 + off, Bl + gidx);
        }
    } else {
        #pragma unroll
        for (int i = 0; i < 2; i++) {
            int s = tid + i * 256;
            int k = s >> 4, ns = s & 15;
            uint32_t off = (uint32_t)(k * 272 + ns * 16);
            size_t gidx = (size_t)(k0 + k) * ldb + col0 + ns * 8;
            cp16(sbuf + 20480 + off, Bh + gidx);
            cp16(sbuf + 30720 + off, Bl + gidx);
        }
    }
    asm volatile("cp.async.commit_group;" ::: "memory");
}

template<bool TRANSB, bool RELU, bool CAUSAL>
__global__ void __launch_bounds__(256)
tmma_k(int K,
       const __nv_bfloat16* __restrict__ Ah, const __nv_bfloat16* __restrict__ Al,
       int lda, long long sAo, long long sAi,
       const __nv_bfloat16* __restrict__ Bh, const __nv_bfloat16* __restrict__ Bl,
       int ldb, long long sBo, long long sBi,
       float* __restrict__ C, __nv_bfloat16* __restrict__ Chi,
       __nv_bfloat16* __restrict__ Clo,
       int ldc, long long sCo, long long sCi,
       const float* __restrict__ bias, float scale, int innerH)
{
    extern __shared__ char smraw[];
    int z  = blockIdx.z;
    int zo = z / innerH, zi = z - zo * innerH;
    Ah += zo * sAo + zi * sAi;  Al += zo * sAo + zi * sAi;
    Bh += zo * sBo + zi * sBi;  Bl += zo * sBo + zi * sBi;
    if (C) C += zo * sCo + zi * sCi;
    if (Chi) { Chi += zo * sCo + zi * sCi; Clo += zo * sCo + zi * sCi; }

    const int tid = threadIdx.x;
    const int lane = tid & 31;
    const int wid  = tid >> 5;
    const int wm = wid >> 2, wn = wid & 3;
    const int row0 = blockIdx.y * 128;
    const int col0 = blockIdx.x * 128;
    const int lr = lane >> 2, lc = lane & 3;
    const int g = lane >> 3, li = lane & 7;

    // fully-masked causal block: skip all compute, emit NEGBIG
    if (CAUSAL && col0 > row0 + 127) {
        #pragma unroll
        for (int mt = 0; mt < 4; mt++) {
            int rb = row0 + wm * 64 + mt * 16 + lr;
            #pragma unroll
            for (int nt = 0; nt < 4; nt++) {
                int cc = col0 + wn * 32 + nt * 8 + 2 * lc;
                #pragma unroll
                for (int half = 0; half < 2; half++) {
                    size_t o = (size_t)(rb + half * 8) * ldc + cc;
                    *(float2*)&C[o] = make_float2(NEGBIG, NEGBIG);
                }
            }
        }
        return;
    }

    const uint32_t sb = smem_u32(smraw);

    // per-lane ldmatrix offsets
    const uint32_t aoff = (uint32_t)((wm * 64 + (g & 1) * 8 + li) * 80 + (g >> 1) * 16);
    uint32_t boff[2];
    #pragma unroll
    for (int p2 = 0; p2 < 2; p2++) {
        if (TRANSB)
            boff[p2] = (uint32_t)((wn * 32 + p2 * 16 + (g >> 1) * 8 + li) * 80 + (g & 1) * 16);
        else
            boff[p2] = (uint32_t)(((g & 1) * 8 + li) * 272 + (wn * 32 + (2 * p2 + (g >> 1)) * 8) * 2);
    }

    float acc[4][4][4];
    #pragma unroll
    for (int i = 0; i < 4; i++)
        #pragma unroll
        for (int j = 0; j < 4; j++)
            #pragma unroll
            for (int q = 0; q < 4; q++) acc[i][j][q] = 0.f;

    const int nch = K / TBK;

    // prologue: stage chunks 0 and 1 (all shapes have nch >= 2)
    stage<TRANSB>(Ah, Al, lda, Bh, Bl, ldb, row0, col0, 0,       sb,          tid);
    stage<TRANSB>(Ah, Al, lda, Bh, Bl, ldb, row0, col0, TBK,     sb + SM_BUF, tid);

    int rbuf = 0, wbuf = 2;
    for (int c = 0; c < nch; c++) {
        asm volatile("cp.async.wait_group 1;" ::: "memory");  // chunk c arrived
        __syncthreads();                                      // all warps see it
        if (c + 2 < nch)
            stage<TRANSB>(Ah, Al, lda, Bh, Bl, ldb, row0, col0,
                          (c + 2) * TBK, sb + (uint32_t)wbuf * SM_BUF, tid);
        else
            asm volatile("cp.async.commit_group;" ::: "memory");  // keep count

        uint32_t sbuf = sb + (uint32_t)rbuf * SM_BUF;

        #pragma unroll
        for (int ks = 0; ks < 2; ks++) {
            uint32_t bh[2][4], bl[2][4];
            #pragma unroll
            for (int p2 = 0; p2 < 2; p2++) {
                uint32_t ba = sbuf + 20480 + boff[p2] +
                              (TRANSB ? (uint32_t)(ks * 32) : (uint32_t)(ks * 16 * 272));
                if (TRANSB) { ldsm4(bh[p2], ba); ldsm4(bl[p2], ba + 10240); }
                else        { ldsm4t(bh[p2], ba); ldsm4t(bl[p2], ba + 10240); }
            }
            #pragma unroll
            for (int mt = 0; mt < 4; mt++) {
                uint32_t aa = sbuf + aoff + (uint32_t)(mt * 16 * 80 + ks * 32);
                uint32_t ah[4], al[4];
                ldsm4(ah, aa);
                ldsm4(al, aa + 10240);
                #pragma unroll
                for (int nt = 0; nt < 4; nt++) {
                    const uint32_t* bhp = &bh[nt >> 1][(nt & 1) * 2];
                    const uint32_t* blp = &bl[nt >> 1][(nt & 1) * 2];
                    mma16(acc[mt][nt], ah, bhp);
                    mma16(acc[mt][nt], ah, blp);
                    mma16(acc[mt][nt], al, bhp);
                }
            }
        }

        rbuf = (rbuf == NSTAGE - 1) ? 0 : rbuf + 1;
        wbuf = (wbuf == NSTAGE - 1) ? 0 : wbuf + 1;
    }

    // ---- epilogue: optional fp32 C and optional hi/lo plane split ----
    #pragma unroll
    for (int mt = 0; mt < 4; mt++) {
        int rb = row0 + wm * 64 + mt * 16 + lr;
        #pragma unroll
        for (int nt = 0; nt < 4; nt++) {
            int cc = col0 + wn * 32 + nt * 8 + 2 * lc;
            #pragma unroll
            for (int half = 0; half < 2; half++) {
                int r = rb + half * 8;
                float v0 = acc[mt][nt][half * 2 + 0] * scale;
                float v1 = acc[mt][nt][half * 2 + 1] * scale;
                if (CAUSAL) {
                    if (cc > r)     v0 += NEGBIG;
                    if (cc + 1 > r) v1 += NEGBIG;
                }
                if (bias) { v0 += bias[cc]; v1 += bias[cc + 1]; }
                if (RELU) { v0 = fmaxf(v0, 0.f); v1 = fmaxf(v1, 0.f); }
                size_t o = (size_t)r * ldc + cc;
                if (C) *(float2*)&C[o] = make_float2(v0, v1);
                if (Chi) {
                    __nv_bfloat16 h0, l0, h1, l1;
                    split1(v0, h0, l0); split1(v1, h1, l1);
                    *(__nv_bfloat162*)&Chi[o] = __halves2bfloat162(h0, h1);
                    *(__nv_bfloat162*)&Clo[o] = __halves2bfloat162(l0, l1);
                }
            }
        }
    }
}

// ================= SIMT GEMM (prenet only: K=234) =============
#define BM 128
#define BN 128
#define BKT 16

__global__ void __launch_bounds__(256)
gemm_nn_k(int M, int N, int K,
          const float* __restrict__ A, int lda,
          const float* __restrict__ B, int ldb,
          __nv_bfloat16* __restrict__ Chi, __nv_bfloat16* __restrict__ Clo,
          int ldc, const float* __restrict__ bias)
{
    __shared__ __align__(16) float As[BKT][BM];
    __shared__ __align__(16) float Bs[BKT][BN];

    int tid = threadIdx.x;
    int tx = tid & 15, ty = tid >> 4;
    int row0 = blockIdx.y * BM, col0 = blockIdx.x * BN;

    float acc[8][8];
    #pragma unroll
    for (int i = 0; i < 8; i++)
        #pragma unroll
        for (int j = 0; j < 8; j++) acc[i][j] = 0.f;

    for (int k0 = 0; k0 < K; k0 += BKT) {
        #pragma unroll
        for (int t = 0; t < 2; t++) {
            int slot = tid + t * 256;
            int r = slot >> 2, cq = slot & 3;
            const float* ap = A + (size_t)(row0 + r) * lda + k0 + cq * 4;
            #pragma unroll
            for (int j = 0; j < 4; j++) {
                int gk = k0 + cq * 4 + j;
                As[cq * 4 + j][r] = (gk < K) ? ap[j] : 0.f;
            }
        }
        #pragma unroll
        for (int t = 0; t < 2; t++) {
            int slot = tid + t * 256;
            int kk = slot >> 5, n4 = slot & 31;
            int gk = k0 + kk;
            const float* bp = B + (size_t)gk * ldb + col0 + n4 * 4;
            #pragma unroll
            for (int j = 0; j < 4; j++)
                Bs[kk][n4 * 4 + j] = (gk < K) ? bp[j] : 0.f;
        }
        __syncthreads();

        #pragma unroll
        for (int kk = 0; kk < BKT; kk++) {
            float4 a0 = *(const float4*)&As[kk][ty * 4];
            float4 a1 = *(const float4*)&As[kk][64 + ty * 4];
            float4 b0 = *(const float4*)&Bs[kk][tx * 4];
            float4 b1 = *(const float4*)&Bs[kk][64 + tx * 4];
            float av[8] = {a0.x, a0.y, a0.z, a0.w, a1.x, a1.y, a1.z, a1.w};
            float bv[8] = {b0.x, b0.y, b0.z, b0.w, b1.x, b1.y, b1.z, b1.w};
            #pragma unroll
            for (int i = 0; i < 8; i++)
                #pragma unroll
                for (int j = 0; j < 8; j++)
                    acc[i][j] += av[i] * bv[j];
        }
        __syncthreads();
    }

    #pragma unroll
    for (int i = 0; i < 8; i++) {
        int r = row0 + ((i < 4) ? (ty * 4 + i) : (64 + ty * 4 + i - 4));
        #pragma unroll
        for (int jb = 0; jb < 2; jb++) {
            int c0 = col0 + jb * 64 + tx * 4;
            size_t o = (size_t)r * ldc + c0;
            #pragma unroll
            for (int j = 0; j < 4; j++) {
                float v = acc[i][jb * 4 + j] + bias[c0 + j];
                __nv_bfloat16 hh, ll;
                split1(v, hh, ll);
                Chi[o + j] = hh; Clo[o + j] = ll;
            }
        }
    }
}

// ---------------- split kernels ----------------
__global__ void split_k(const float* __restrict__ src,
                        __nv_bfloat16* __restrict__ hi,
                        __nv_bfloat16* __restrict__ lo, int n)
{
    int i = blockIdx.x * blockDim.x + threadIdx.x;
    if (i >= n) return;
    split1(src[i], hi[i], lo[i]);
}

__global__ void copy_split_k(float* __restrict__ dst, const float* __restrict__ src,
                             __nv_bfloat16* __restrict__ hi,
                             __nv_bfloat16* __restrict__ lo, int n)
{
    int i = blockIdx.x * blockDim.x + threadIdx.x;
    if (i >= n) return;
    float v = src[i];
    dst[i] = v;
    split1(v, hi[i], lo[i]);
}

// ---------------- block reduce ----------------
__device__ __forceinline__ float blockReduceSum(float v, float* s) {
    int tid = threadIdx.x;
    int nw = blockDim.x >> 5;
    #pragma unroll
    for (int o = 16; o; o >>= 1) v += __shfl_xor_sync(0xffffffffu, v, o);
    if ((tid & 31) == 0) s[tid >> 5] = v;
    __syncthreads();
    if (tid < 32) {
        float t = (tid < nw) ? s[tid] : 0.f;
        #pragma unroll
        for (int o = 16; o; o >>= 1) t += __shfl_xor_sync(0xffffffffu, t, o);
        if (tid == 0) s[0] = t;
    }
    __syncthreads();
    float r = s[0];
    __syncthreads();
    return r;
}

// ---------------- register-resident softmax for 512 cols ----------------
// reads fp32 scores, writes ONLY the hi/lo planes (no fp32 round-trip).
__global__ void softmax512_k(const float* __restrict__ x,
                             __nv_bfloat16* __restrict__ hi,
                             __nv_bfloat16* __restrict__ lo)
{
    size_t base = (size_t)blockIdx.x * 512;
    int tid = threadIdx.x;
    __shared__ float red[32];

    float v0 = x[base + tid];
    float v1 = x[base + tid + 256];

    float mx = fmaxf(v0, v1);
    #pragma unroll
    for (int o = 16; o; o >>= 1) mx = fmaxf(mx, __shfl_xor_sync(0xffffffffu, mx, o));
    if ((tid & 31) == 0) red[tid >> 5] = mx;
    __syncthreads();
    if (tid < 32) {
        float t = (tid < 8) ? red[tid] : -3.4e38f;
        #pragma unroll
        for (int o = 16; o; o >>= 1) t = fmaxf(t, __shfl_xor_sync(0xffffffffu, t, o));
        if (tid == 0) red[0] = t;
    }
    __syncthreads();
    mx = red[0];
    __syncthreads();

    float e0 = expf(v0 - mx);
    float e1 = expf(v1 - mx);
    float sum = blockReduceSum(e0 + e1, red);
    float inv = 1.f / sum;

    __nv_bfloat16 hh, ll;
    split1(e0 * inv, hh, ll);
    hi[base + tid] = hh; lo[base + tid] = ll;
    split1(e1 * inv, hh, ll);
    hi[base + tid + 256] = hh; lo[base + tid + 256] = ll;
}

// ---------------- fused x = LayerNorm(x + h) (+ split planes) ---------------
__global__ void add_ln_k(float* __restrict__ x, const float* __restrict__ h,
                         __nv_bfloat16* __restrict__ hi, __nv_bfloat16* __restrict__ lo,
                         const float* __restrict__ g, const float* __restrict__ b,
                         int ncols)
{
    size_t base = (size_t)blockIdx.x * ncols;
    int tid = threadIdx.x;
    __shared__ float red[32];

    float v[4];
    float sum = 0.f;
    int c = 0;
    for (int i = tid; i < ncols; i += blockDim.x, c++) {
        v[c] = x[base + i] + h[base + i];
        sum += v[c];
    }
    sum = blockReduceSum(sum, red);
    float mu = sum / ncols;

    float sq = 0.f;
    c = 0;
    for (int i = tid; i < ncols; i += blockDim.x, c++) {
        float d = v[c] - mu;
        sq += d * d;
    }
    sq = blockReduceSum(sq, red);
    float rstd = rsqrtf(sq / ncols + 1e-5f);

    c = 0;
    for (int i = tid; i < ncols; i += blockDim.x, c++) {
        float o = (v[c] - mu) * rstd * g[i] + b[i];
        x[base + i] = o;
        split1(o, hi[base + i], lo[base + i]);
    }
}

// ---------------- scheduled sampling mix (+ split planes) ----------------
__global__ void mix_k(float* __restrict__ x, const float* __restrict__ labels,
                      __nv_bfloat16* __restrict__ hi, __nv_bfloat16* __restrict__ lo,
                      const float* __restrict__ sr, const int* __restrict__ steps,
                      int total)
{
    int i = blockIdx.x * blockDim.x + threadIdx.x;
    if (i >= total) return;
    int s = (i / cE) % cS;
    int b = i / (cE * cS);
    float thr = (float)(*steps) / 200000.0f;
    float v = (sr[s * cB + b] >= thr) ? labels[i] : x[i];
    x[i] = v;
    split1(v, hi[i], lo[i]);
}

// ---------------- host dispatch ----------------
struct Planes { const __nv_bfloat16 *h, *l; };

static void launch_tmma(bool transB, bool relu, bool causal,
                        int M, int N, int K,
                        Planes A, int lda, long long sAo, long long sAi,
                        Planes B, int ldb, long long sBo, long long sBi,
                        float* C, __nv_bfloat16* Chi, __nv_bfloat16* Clo,
                        int ldc, long long sCo, long long sCi,
                        const float* bias, float scale, int nz, int innerH)
{
    dim3 blk(256);
    dim3 grd(N / 128, M / 128, nz);
    if (!transB) {
        cudaFuncSetAttribute((const void*)tmma_k<false, false, false>,
                             cudaFuncAttributeMaxDynamicSharedMemorySize, TSMEM);
        tmma_k<false, false, false><<<grd, blk, TSMEM>>>(K, A.h, A.l, lda, sAo, sAi,
            B.h, B.l, ldb, sBo, sBi, C, Chi, Clo, ldc, sCo, sCi, bias, scale, innerH);
    } else if (causal) {
        cudaFuncSetAttribute((const void*)tmma_k<true, false, true>,
                             cudaFuncAttributeMaxDynamicSharedMemorySize, TSMEM);
        tmma_k<true, false, true><<<grd, blk, TSMEM>>>(K, A.h, A.l, lda, sAo, sAi,
            B.h, B.l, ldb, sBo, sBi, C, Chi, Clo, ldc, sCo, sCi, bias, scale, innerH);
    } else if (relu) {
        cudaFuncSetAttribute((const void*)tmma_k<true, true, false>,
                             cudaFuncAttributeMaxDynamicSharedMemorySize, TSMEM);
        tmma_k<true, true, false><<<grd, blk, TSMEM>>>(K, A.h, A.l, lda, sAo, sAi,
            B.h, B.l, ldb, sBo, sBi, C, Chi, Clo, ldc, sCo, sCi, bias, scale, innerH);
    } else {
        cudaFuncSetAttribute((const void*)tmma_k<true, false, false>,
                             cudaFuncAttributeMaxDynamicSharedMemorySize, TSMEM);
        tmma_k<true, false, false><<<grd, blk, TSMEM>>>(K, A.h, A.l, lda, sAo, sAi,
            B.h, B.l, ldb, sBo, sBi, C, Chi, Clo, ldc, sCo, sCi, bias, scale, innerH);
    }
}

template<typename T>
static T* sym(T* symbol) {
    void* p = nullptr;
    cudaGetSymbolAddress(&p, (const void*)symbol);
    return (T*)p;
}

extern "C" void kernel_launch(void* const* d_in, const int* in_sizes, int n_in,
                              void* d_out, int out_size)
{
    const float* batch    = (const float*)d_in[0];
    const float* labels   = (const float*)d_in[1];
    const float* sched    = (const float*)d_in[2];
    const int*   steps    = (const int*)  d_in[3];
    const float* W_pre    = (const float*)d_in[4];
    const float* b_pre    = (const float*)d_in[5];
    const float* W_enc    = (const float*)d_in[6];
    const float* b_enc    = (const float*)d_in[7];
    const float* W_e2d    = (const float*)d_in[8];
    const float* b_e2d    = (const float*)d_in[9];
    const float* sa_in_w  = (const float*)d_in[10];
    const float* sa_in_b  = (const float*)d_in[11];
    const float* sa_out_w = (const float*)d_in[12];
    const float* sa_out_b = (const float*)d_in[13];
    const float* ca_in_w  = (const float*)d_in[14];
    const float* ca_in_b  = (const float*)d_in[15];
    const float* ca_out_w = (const float*)d_in[16];
    const float* ca_out_b = (const float*)d_in[17];
    const float* w1       = (const float*)d_in[18];
    const float* b1       = (const float*)d_in[19];
    const float* w2       = (const float*)d_in[20];
    const float* b2       = (const float*)d_in[21];
    const float* g1       = (const float*)d_in[22];
    const float* be1      = (const float*)d_in[23];
    const float* g2       = (const float*)d_in[24];
    const float* be2      = (const float*)d_in[25];
    const float* g3       = (const float*)d_in[26];
    const float* be3      = (const float*)d_in[27];

    float* x  = sym(g_x);
    float* h  = sym(g_h);
    float* sc = sym(g_sc);

    __nv_bfloat16 *xh = sym(x_h), *xl = sym(x_l);
    __nv_bfloat16 *ah = sym(a_h), *al = sym(a_l);
    __nv_bfloat16 *memh = sym(mem_h), *meml = sym(mem_l);
    __nv_bfloat16 *ench = sym(enc_h), *encl = sym(enc_l);
    __nv_bfloat16 *qkvh = sym(qkv_h), *qkvl = sym(qkv_l);
    __nv_bfloat16 *sch = sym(sc_h), *scl = sym(sc_l);
    __nv_bfloat16 *cakvh = sym(cakv_h), *cakvl = sym(cakv_l);
    __nv_bfloat16 *wsaih = sym(wsai_h), *wsail = sym(wsai_l);
    __nv_bfloat16 *wsaoh = sym(wsao_h), *wsaol = sym(wsao_l);
    __nv_bfloat16 *wcaih = sym(wcai_h), *wcail = sym(wcai_l);
    __nv_bfloat16 *wcaoh = sym(wcao_h), *wcaol = sym(wcao_l);
    __nv_bfloat16 *ww1h = sym(ww1_h), *ww1l = sym(ww1_l);
    __nv_bfloat16 *ww2h = sym(ww2_h), *ww2l = sym(ww2_l);
    __nv_bfloat16 *wench = sym(wenc_h), *wencl = sym(wenc_l);
    __nv_bfloat16 *we2dh = sym(we2d_h), *we2dl = sym(we2d_l);

    const float atscale = 1.0f / sqrtf((float)cHD);
    const long long sQb  = (long long)cS * 3 * cE;
    const long long sKVb = (long long)cS * 2 * cE;
    const long long sScb = (long long)cH * cS * cS;
    const long long sSch = (long long)cS * cS;
    const long long sAb  = (long long)cS * cE;

    // ---- weight splits (once per call) ----
    auto spl = [](const float* s, __nv_bfloat16* hh, __nv_bfloat16* ll, int n) {
        split_k<<<(n + 255) / 256, 256>>>(s, hh, ll, n);
    };
    spl(sa_in_w,  wsaih, wsail, cL * 3 * cE * cE);
    spl(sa_out_w, wsaoh, wsaol, cL * cE * cE);
    spl(ca_in_w,  wcaih, wcail, cL * 3 * cE * cE);
    spl(ca_out_w, wcaoh, wcaol, cL * cE * cE);
    spl(w1, ww1h, ww1l, cL * cFF * cE);
    spl(w2, ww2h, ww2l, cL * cE * cFF);
    spl(W_enc, wench, wencl, cE * cENC);
    spl(W_e2d, we2dh, we2dl, cENC * cE);

    // ---- prenet (SIMT, K=234, planes only) + encoder chain (NN tensor) ----
    {
        dim3 blk(256), grd(cE / BN, cM / BM, 1);
        gemm_nn_k<<<grd, blk>>>(cM, cE, cIN, batch, cIN, W_pre, cE,
                                ah, al, cE, b_pre);
    }
    launch_tmma(false, false, false, cM, cENC, cE,
                {ah, al}, cE, 0, 0, {wench, wencl}, cENC, 0, 0,
                nullptr, ench, encl, cENC, 0, 0, b_enc, 1.f, 1, 1);
    launch_tmma(false, false, false, cM, cE, cENC,
                {ench, encl}, cENC, 0, 0, {we2dh, we2dl}, cE, 0, 0,
                nullptr, memh, meml, cE, 0, 0, b_e2d, 1.f, 1, 1);

    {
        int total = cM * cE;
        copy_split_k<<<(total + 255) / 256, 256>>>(x, labels, xh, xl, total);
    }

    for (int p = 0; p < 2; p++) {
        for (int l = 0; l < cL; l++) {
            size_t wqkvOff = (size_t)l * 3 * cE * cE;
            size_t woOff   = (size_t)l * cE * cE;
            const float* sib = sa_in_b + (size_t)l * 3 * cE;
            const float* cib = ca_in_b + (size_t)l * 3 * cE;
            size_t kvOff = (size_t)l * cM * 2 * cE;

            // ===== self-attention =====
            launch_tmma(true, false, false, cM, 3 * cE, cE,
                        {xh, xl}, cE, 0, 0,
                        {wsaih + wqkvOff, wsail + wqkvOff}, cE, 0, 0,
                        nullptr, qkvh, qkvl, 3 * cE, 0, 0, sib, 1.f, 1, 1);
            launch_tmma(true, false, true, cS, cS, cHD,
                        {qkvh, qkvl}, 3 * cE, sQb, cHD,
                        {qkvh + cE, qkvl + cE}, 3 * cE, sQb, cHD,
                        sc, nullptr, nullptr, cS, sScb, sSch, nullptr, atscale,
                        cB * cH, cH);
            softmax512_k<<<cB * cH * cS, 256>>>(sc, sch, scl);
            launch_tmma(false, false, false, cS, cHD, cS,
                        {sch, scl}, cS, sScb, sSch,
                        {qkvh + 2 * cE, qkvl + 2 * cE}, 3 * cE, sQb, cHD,
                        nullptr, ah, al, cE, sAb, cHD, nullptr, 1.f, cB * cH, cH);
            launch_tmma(true, false, false, cM, cE, cE,
                        {ah, al}, cE, 0, 0,
                        {wsaoh + woOff, wsaol + woOff}, cE, 0, 0,
                        h, nullptr, nullptr, cE, 0, 0,
                        sa_out_b + (size_t)l * cE, 1.f, 1, 1);
            add_ln_k<<<cM, 256>>>(x, h, xh, xl,
                                  g1 + (size_t)l * cE, be1 + (size_t)l * cE, cE);

            // ===== cross-attention (K/V cached across passes) =====
            launch_tmma(true, false, false, cM, cE, cE,
                        {xh, xl}, cE, 0, 0,
                        {wcaih + wqkvOff, wcail + wqkvOff}, cE, 0, 0,
                        nullptr, qkvh, qkvl, 3 * cE, 0, 0, cib, 1.f, 1, 1);
            if (p == 0)
                launch_tmma(true, false, false, cM, 2 * cE, cE,
                            {memh, meml}, cE, 0, 0,
                            {wcaih + wqkvOff + (size_t)cE * cE,
                             wcail + wqkvOff + (size_t)cE * cE}, cE, 0, 0,
                            nullptr, cakvh + kvOff, cakvl + kvOff,
                            2 * cE, 0, 0, cib + cE, 1.f, 1, 1);
            launch_tmma(true, false, false, cS, cS, cHD,
                        {qkvh, qkvl}, 3 * cE, sQb, cHD,
                        {cakvh + kvOff, cakvl + kvOff}, 2 * cE, sKVb, cHD,
                        sc, nullptr, nullptr, cS, sScb, sSch, nullptr, atscale,
                        cB * cH, cH);
            softmax512_k<<<cB * cH * cS, 256>>>(sc, sch, scl);
            launch_tmma(false, false, false, cS, cHD, cS,
                        {sch, scl}, cS, sScb, sSch,
                        {cakvh + kvOff + cE, cakvl + kvOff + cE}, 2 * cE, sKVb, cHD,
                        nullptr, ah, al, cE, sAb, cHD, nullptr, 1.f, cB * cH, cH);
            launch_tmma(true, false, false, cM, cE, cE,
                        {ah, al}, cE, 0, 0,
                        {wcaoh + woOff, wcaol + woOff}, cE, 0, 0,
                        h, nullptr, nullptr, cE, 0, 0,
                        ca_out_b + (size_t)l * cE, 1.f, 1, 1);
            add_ln_k<<<cM, 256>>>(x, h, xh, xl,
                                  g2 + (size_t)l * cE, be2 + (size_t)l * cE, cE);

            // ===== FFN (relu) — hidden planes reuse qkv plane buffers =====
            launch_tmma(true, true, false, cM, cFF, cE,
                        {xh, xl}, cE, 0, 0,
                        {ww1h + (size_t)l * cFF * cE, ww1l + (size_t)l * cFF * cE},
                        cE, 0, 0,
                        nullptr, qkvh, qkvl, cFF, 0, 0, b1 + (size_t)l * cFF, 1.f, 1, 1);
            launch_tmma(true, false, false, cM, cE, cFF,
                        {qkvh, qkvl}, cFF, 0, 0,
                        {ww2h + (size_t)l * cE * cFF, ww2l + (size_t)l * cE * cFF},
                        cFF, 0, 0,
                        h, nullptr, nullptr, cE, 0, 0, b2 + (size_t)l * cE, 1.f, 1, 1);
            add_ln_k<<<cM, 256>>>(x, h, xh, xl,
                                  g3 + (size_t)l * cE, be3 + (size_t)l * cE, cE);
        }
        if (p == 0) {
            int total = cM * cE;
            mix_k<<<(total + 255) / 256, 256>>>(x, labels, xh, xl, sched, steps, total);
        }
    }

    cudaMemcpyAsync(d_out, x, sizeof(float) * (size_t)cM * cE,
                    cudaMemcpyDeviceToDevice);
}

// round 17
// speedup vs baseline: 1.5830x; 1.0109x over previous
#include <cuda_runtime.h>
#include <cuda_bf16.h>
#include <math.h>
#include <stdint.h>

// ---------------- problem constants ----------------
constexpr int cB = 16, cS = 512, cE = 768, cH = 2, cHD = 384;
constexpr int cFF = 256, cL = 3, cENC = 128, cIN = 234;
constexpr int cM = cB * cS;
constexpr float NEGBIG = -1e9f;

// ---------------- fp32 scratch (only what is actually read as fp32) --------
__device__ float g_x  [cM * cE];
__device__ float g_h  [cM * cE];
__device__ float g_sc [cB * cH * cS * cS];

// ---------------- bf16 hi/lo planes (activations) ----------------
__device__ __nv_bfloat16 x_h[cM * cE],      x_l[cM * cE];
__device__ __nv_bfloat16 a_h[cM * cE],      a_l[cM * cE];
__device__ __nv_bfloat16 mem_h[cM * cE],    mem_l[cM * cE];
__device__ __nv_bfloat16 enc_h[cM * cENC],  enc_l[cM * cENC];
__device__ __nv_bfloat16 qkv_h[cM * 3 * cE], qkv_l[cM * 3 * cE];
__device__ __nv_bfloat16 sc_h[cB * cH * cS * cS], sc_l[cB * cH * cS * cS];
__device__ __nv_bfloat16 cakv_h[cL * cM * 2 * cE], cakv_l[cL * cM * 2 * cE];
// ---------------- bf16 hi/lo planes (weights, split once per call) ----------
__device__ __nv_bfloat16 wsai_h[cL * 3 * cE * cE], wsai_l[cL * 3 * cE * cE];
__device__ __nv_bfloat16 wsao_h[cL * cE * cE],     wsao_l[cL * cE * cE];
__device__ __nv_bfloat16 wcai_h[cL * 3 * cE * cE], wcai_l[cL * 3 * cE * cE];
__device__ __nv_bfloat16 wcao_h[cL * cE * cE],     wcao_l[cL * cE * cE];
__device__ __nv_bfloat16 ww1_h[cL * cFF * cE],     ww1_l[cL * cFF * cE];
__device__ __nv_bfloat16 ww2_h[cL * cE * cFF],     ww2_l[cL * cE * cFF];
__device__ __nv_bfloat16 wenc_h[cE * cENC],        wenc_l[cE * cENC];
__device__ __nv_bfloat16 we2d_h[cENC * cE],        we2d_l[cENC * cE];

__device__ __forceinline__ void split1(float v, __nv_bfloat16& h, __nv_bfloat16& l) {
    h = __float2bfloat16_rn(v);
    l = __float2bfloat16_rn(v - __bfloat162float(h));
}

// ============ bf16-plane mma.sync GEMM =================
// C = A * op(B). 128x128 CTA tile, 256 thr, 8 warps (2x4), warp tile 64x32.
// Inputs are pre-split bf16 hi/lo planes; D += Ah*Bh + Ah*Bl + Al*Bh.
// 3-stage cp.async pipeline, ONE __syncthreads per chunk:
//   [wait_group 1 -> barrier -> issue stage c+2 -> compute c]
// fp32 C and hi/lo plane outputs are BOTH optional (nullable).
// CAUSAL: output blocks fully above the diagonal early-exit with NEGBIG.
// CAUSALA: A is a causal-softmax matrix (exact zeros for k > row) -> trim the
//          K loop to k0 <= row0+127 chunks (contributions are exact +0.0).
// NOTE: no minBlocksPerMultiprocessor — forcing 2 CTAs/SM (regs<=128) spills.
// M, N multiples of 128; K multiple of 32 (and effective K/32 >= 2).

constexpr int TBK = 32;
// per-buffer smem layout (bytes): Ahi 0 (128 rows x 80B), Alo 10240,
// Bhi 20480, Blo 30720. TN B: 128n x 80B rows. NN B: 32k x 272B rows.
constexpr int SM_BUF = 40960;
constexpr int NSTAGE = 3;
constexpr int TSMEM  = NSTAGE * SM_BUF;   // 122880 (1 CTA/SM)

__device__ __forceinline__ uint32_t smem_u32(const void* p) {
    uint32_t a;
    asm("{ .reg .u64 t; cvta.to.shared.u64 t, %1; cvt.u32.u64 %0, t; }"
        : "=r"(a) : "l"(p));
    return a;
}
__device__ __forceinline__ void cp16(uint32_t s, const void* g) {
    asm volatile("cp.async.ca.shared.global [%0], [%1], 16;"
                 :: "r"(s), "l"(g) : "memory");
}
__device__ __forceinline__ void ldsm4(uint32_t* r, uint32_t a) {
    asm volatile("ldmatrix.sync.aligned.m8n8.x4.shared.b16 {%0,%1,%2,%3}, [%4];"
        : "=r"(r[0]), "=r"(r[1]), "=r"(r[2]), "=r"(r[3]) : "r"(a));
}
__device__ __forceinline__ void ldsm4t(uint32_t* r, uint32_t a) {
    asm volatile("ldmatrix.sync.aligned.m8n8.x4.trans.shared.b16 {%0,%1,%2,%3}, [%4];"
        : "=r"(r[0]), "=r"(r[1]), "=r"(r[2]), "=r"(r[3]) : "r"(a));
}
__device__ __forceinline__ void mma16(float* d, const uint32_t* a, const uint32_t* b) {
    asm volatile(
        "mma.sync.aligned.m16n8k16.row.col.f32.bf16.bf16.f32 "
        "{%0,%1,%2,%3}, {%4,%5,%6,%7}, {%8,%9}, {%0,%1,%2,%3};"
        : "+f"(d[0]), "+f"(d[1]), "+f"(d[2]), "+f"(d[3])
        : "r"(a[0]), "r"(a[1]), "r"(a[2]), "r"(a[3]), "r"(b[0]), "r"(b[1]));
}

template<bool TRANSB>
__device__ __forceinline__ void stage(
    const __nv_bfloat16* __restrict__ Ah, const __nv_bfloat16* __restrict__ Al, int lda,
    const __nv_bfloat16* __restrict__ Bh, const __nv_bfloat16* __restrict__ Bl, int ldb,
    int row0, int col0, int k0, uint32_t sbuf, int tid)
{
    #pragma unroll
    for (int i = 0; i < 2; i++) {
        int s = tid + i * 256;
        int r = s >> 2, kq = s & 3;
        uint32_t off = (uint32_t)(r * 80 + kq * 16);
        size_t gidx = (size_t)(row0 + r) * lda + k0 + kq * 8;
        cp16(sbuf + off,         Ah + gidx);
        cp16(sbuf + 10240 + off, Al + gidx);
    }
    if (TRANSB) {
        #pragma unroll
        for (int i = 0; i < 2; i++) {
            int s = tid + i * 256;
            int n = s >> 2, kq = s & 3;
            uint32_t off = (uint32_t)(n * 80 + kq * 16);
            size_t gidx = (size_t)(col0 + n) * ldb + k0 + kq * 8;
            cp16(sbuf + 20480 + off, Bh + gidx);
            cp16(sbuf + 30720 + off, Bl + gidx);
        }
    } else {
        #pragma unroll
        for (int i = 0; i < 2; i++) {
            int s = tid + i * 256;
            int k = s >> 4, ns = s & 15;
            uint32_t off = (uint32_t)(k * 272 + ns * 16);
            size_t gidx = (size_t)(k0 + k) * ldb + col0 + ns * 8;
            cp16(sbuf + 20480 + off, Bh + gidx);
            cp16(sbuf + 30720 + off, Bl + gidx);
        }
    }
    asm volatile("cp.async.commit_group;" ::: "memory");
}

template<bool TRANSB, bool RELU, bool CAUSAL, bool CAUSALA>
__global__ void __launch_bounds__(256)
tmma_k(int K,
       const __nv_bfloat16* __restrict__ Ah, const __nv_bfloat16* __restrict__ Al,
       int lda, long long sAo, long long sAi,
       const __nv_bfloat16* __restrict__ Bh, const __nv_bfloat16* __restrict__ Bl,
       int ldb, long long sBo, long long sBi,
       float* __restrict__ C, __nv_bfloat16* __restrict__ Chi,
       __nv_bfloat16* __restrict__ Clo,
       int ldc, long long sCo, long long sCi,
       const float* __restrict__ bias, float scale, int innerH)
{
    extern __shared__ char smraw[];
    int z  = blockIdx.z;
    int zo = z / innerH, zi = z - zo * innerH;
    Ah += zo * sAo + zi * sAi;  Al += zo * sAo + zi * sAi;
    Bh += zo * sBo + zi * sBi;  Bl += zo * sBo + zi * sBi;
    if (C) C += zo * sCo + zi * sCi;
    if (Chi) { Chi += zo * sCo + zi * sCi; Clo += zo * sCo + zi * sCi; }

    const int tid = threadIdx.x;
    const int lane = tid & 31;
    const int wid  = tid >> 5;
    const int wm = wid >> 2, wn = wid & 3;
    const int row0 = blockIdx.y * 128;
    const int col0 = blockIdx.x * 128;
    const int lr = lane >> 2, lc = lane & 3;
    const int g = lane >> 3, li = lane & 7;

    // fully-masked causal block: skip all compute, emit NEGBIG
    if (CAUSAL && col0 > row0 + 127) {
        #pragma unroll
        for (int mt = 0; mt < 4; mt++) {
            int rb = row0 + wm * 64 + mt * 16 + lr;
            #pragma unroll
            for (int nt = 0; nt < 4; nt++) {
                int cc = col0 + wn * 32 + nt * 8 + 2 * lc;
                #pragma unroll
                for (int half = 0; half < 2; half++) {
                    size_t o = (size_t)(rb + half * 8) * ldc + cc;
                    *(float2*)&C[o] = make_float2(NEGBIG, NEGBIG);
                }
            }
        }
        return;
    }

    const uint32_t sb = smem_u32(smraw);

    // per-lane ldmatrix offsets
    const uint32_t aoff = (uint32_t)((wm * 64 + (g & 1) * 8 + li) * 80 + (g >> 1) * 16);
    uint32_t boff[2];
    #pragma unroll
    for (int p2 = 0; p2 < 2; p2++) {
        if (TRANSB)
            boff[p2] = (uint32_t)((wn * 32 + p2 * 16 + (g >> 1) * 8 + li) * 80 + (g & 1) * 16);
        else
            boff[p2] = (uint32_t)(((g & 1) * 8 + li) * 272 + (wn * 32 + (2 * p2 + (g >> 1)) * 8) * 2);
    }

    float acc[4][4][4];
    #pragma unroll
    for (int i = 0; i < 4; i++)
        #pragma unroll
        for (int j = 0; j < 4; j++)
            #pragma unroll
            for (int q = 0; q < 4; q++) acc[i][j][q] = 0.f;

    int nch = K / TBK;
    // A is causal softmax output: rows r have exact 0 for k > r, so chunks
    // with k0 >= row0+128 contribute exact +0.0 to acc -> trim (bit-exact).
    if (CAUSALA) {
        int lim = (row0 + 128) / TBK;     // row0+128 is a multiple of TBK
        if (lim < nch) nch = lim;         // lim >= 4 >= pipeline minimum of 2
    }

    // prologue: stage chunks 0 and 1 (all shapes have nch >= 2)
    stage<TRANSB>(Ah, Al, lda, Bh, Bl, ldb, row0, col0, 0,       sb,          tid);
    stage<TRANSB>(Ah, Al, lda, Bh, Bl, ldb, row0, col0, TBK,     sb + SM_BUF, tid);

    int rbuf = 0, wbuf = 2;
    for (int c = 0; c < nch; c++) {
        asm volatile("cp.async.wait_group 1;" ::: "memory");  // chunk c arrived
        __syncthreads();                                      // all warps see it
        if (c + 2 < nch)
            stage<TRANSB>(Ah, Al, lda, Bh, Bl, ldb, row0, col0,
                          (c + 2) * TBK, sb + (uint32_t)wbuf * SM_BUF, tid);
        else
            asm volatile("cp.async.commit_group;" ::: "memory");  // keep count

        uint32_t sbuf = sb + (uint32_t)rbuf * SM_BUF;

        #pragma unroll
        for (int ks = 0; ks < 2; ks++) {
            uint32_t bh[2][4], bl[2][4];
            #pragma unroll
            for (int p2 = 0; p2 < 2; p2++) {
                uint32_t ba = sbuf + 20480 + boff[p2] +
                              (TRANSB ? (uint32_t)(ks * 32) : (uint32_t)(ks * 16 * 272));
                if (TRANSB) { ldsm4(bh[p2], ba); ldsm4(bl[p2], ba + 10240); }
                else        { ldsm4t(bh[p2], ba); ldsm4t(bl[p2], ba + 10240); }
            }
            #pragma unroll
            for (int mt = 0; mt < 4; mt++) {
                uint32_t aa = sbuf + aoff + (uint32_t)(mt * 16 * 80 + ks * 32);
                uint32_t ah[4], al[4];
                ldsm4(ah, aa);
                ldsm4(al, aa + 10240);
                #pragma unroll
                for (int nt = 0; nt < 4; nt++) {
                    const uint32_t* bhp = &bh[nt >> 1][(nt & 1) * 2];
                    const uint32_t* blp = &bl[nt >> 1][(nt & 1) * 2];
                    mma16(acc[mt][nt], ah, bhp);
                    mma16(acc[mt][nt], ah, blp);
                    mma16(acc[mt][nt], al, bhp);
                }
            }
        }

        rbuf = (rbuf == NSTAGE - 1) ? 0 : rbuf + 1;
        wbuf = (wbuf == NSTAGE - 1) ? 0 : wbuf + 1;
    }

    // ---- epilogue: optional fp32 C and optional hi/lo plane split ----
    #pragma unroll
    for (int mt = 0; mt < 4; mt++) {
        int rb = row0 + wm * 64 + mt * 16 + lr;
        #pragma unroll
        for (int nt = 0; nt < 4; nt++) {
            int cc = col0 + wn * 32 + nt * 8 + 2 * lc;
            #pragma unroll
            for (int half = 0; half < 2; half++) {
                int r = rb + half * 8;
                float v0 = acc[mt][nt][half * 2 + 0] * scale;
                float v1 = acc[mt][nt][half * 2 + 1] * scale;
                if (CAUSAL) {
                    if (cc > r)     v0 += NEGBIG;
                    if (cc + 1 > r) v1 += NEGBIG;
                }
                if (bias) { v0 += bias[cc]; v1 += bias[cc + 1]; }
                if (RELU) { v0 = fmaxf(v0, 0.f); v1 = fmaxf(v1, 0.f); }
                size_t o = (size_t)r * ldc + cc;
                if (C) *(float2*)&C[o] = make_float2(v0, v1);
                if (Chi) {
                    __nv_bfloat16 h0, l0, h1, l1;
                    split1(v0, h0, l0); split1(v1, h1, l1);
                    *(__nv_bfloat162*)&Chi[o] = __halves2bfloat162(h0, h1);
                    *(__nv_bfloat162*)&Clo[o] = __halves2bfloat162(l0, l1);
                }
            }
        }
    }
}

// ================= SIMT GEMM (prenet only: K=234) =============
#define BM 128
#define BN 128
#define BKT 16

__global__ void __launch_bounds__(256)
gemm_nn_k(int M, int N, int K,
          const float* __restrict__ A, int lda,
          const float* __restrict__ B, int ldb,
          __nv_bfloat16* __restrict__ Chi, __nv_bfloat16* __restrict__ Clo,
          int ldc, const float* __restrict__ bias)
{
    __shared__ __align__(16) float As[BKT][BM];
    __shared__ __align__(16) float Bs[BKT][BN];

    int tid = threadIdx.x;
    int tx = tid & 15, ty = tid >> 4;
    int row0 = blockIdx.y * BM, col0 = blockIdx.x * BN;

    float acc[8][8];
    #pragma unroll
    for (int i = 0; i < 8; i++)
        #pragma unroll
        for (int j = 0; j < 8; j++) acc[i][j] = 0.f;

    for (int k0 = 0; k0 < K; k0 += BKT) {
        #pragma unroll
        for (int t = 0; t < 2; t++) {
            int slot = tid + t * 256;
            int r = slot >> 2, cq = slot & 3;
            const float* ap = A + (size_t)(row0 + r) * lda + k0 + cq * 4;
            #pragma unroll
            for (int j = 0; j < 4; j++) {
                int gk = k0 + cq * 4 + j;
                As[cq * 4 + j][r] = (gk < K) ? ap[j] : 0.f;
            }
        }
        #pragma unroll
        for (int t = 0; t < 2; t++) {
            int slot = tid + t * 256;
            int kk = slot >> 5, n4 = slot & 31;
            int gk = k0 + kk;
            const float* bp = B + (size_t)gk * ldb + col0 + n4 * 4;
            #pragma unroll
            for (int j = 0; j < 4; j++)
                Bs[kk][n4 * 4 + j] = (gk < K) ? bp[j] : 0.f;
        }
        __syncthreads();

        #pragma unroll
        for (int kk = 0; kk < BKT; kk++) {
            float4 a0 = *(const float4*)&As[kk][ty * 4];
            float4 a1 = *(const float4*)&As[kk][64 + ty * 4];
            float4 b0 = *(const float4*)&Bs[kk][tx * 4];
            float4 b1 = *(const float4*)&Bs[kk][64 + tx * 4];
            float av[8] = {a0.x, a0.y, a0.z, a0.w, a1.x, a1.y, a1.z, a1.w};
            float bv[8] = {b0.x, b0.y, b0.z, b0.w, b1.x, b1.y, b1.z, b1.w};
            #pragma unroll
            for (int i = 0; i < 8; i++)
                #pragma unroll
                for (int j = 0; j < 8; j++)
                    acc[i][j] += av[i] * bv[j];
        }
        __syncthreads();
    }

    #pragma unroll
    for (int i = 0; i < 8; i++) {
        int r = row0 + ((i < 4) ? (ty * 4 + i) : (64 + ty * 4 + i - 4));
        #pragma unroll
        for (int jb = 0; jb < 2; jb++) {
            int c0 = col0 + jb * 64 + tx * 4;
            size_t o = (size_t)r * ldc + c0;
            #pragma unroll
            for (int j = 0; j < 4; j++) {
                float v = acc[i][jb * 4 + j] + bias[c0 + j];
                __nv_bfloat16 hh, ll;
                split1(v, hh, ll);
                Chi[o + j] = hh; Clo[o + j] = ll;
            }
        }
    }
}

// ---------------- split kernels ----------------
__global__ void split_k(const float* __restrict__ src,
                        __nv_bfloat16* __restrict__ hi,
                        __nv_bfloat16* __restrict__ lo, int n)
{
    int i = blockIdx.x * blockDim.x + threadIdx.x;
    if (i >= n) return;
    split1(src[i], hi[i], lo[i]);
}

__global__ void copy_split_k(float* __restrict__ dst, const float* __restrict__ src,
                             __nv_bfloat16* __restrict__ hi,
                             __nv_bfloat16* __restrict__ lo, int n)
{
    int i = blockIdx.x * blockDim.x + threadIdx.x;
    if (i >= n) return;
    float v = src[i];
    dst[i] = v;
    split1(v, hi[i], lo[i]);
}

// ---------------- block reduce ----------------
__device__ __forceinline__ float blockReduceSum(float v, float* s) {
    int tid = threadIdx.x;
    int nw = blockDim.x >> 5;
    #pragma unroll
    for (int o = 16; o; o >>= 1) v += __shfl_xor_sync(0xffffffffu, v, o);
    if ((tid & 31) == 0) s[tid >> 5] = v;
    __syncthreads();
    if (tid < 32) {
        float t = (tid < nw) ? s[tid] : 0.f;
        #pragma unroll
        for (int o = 16; o; o >>= 1) t += __shfl_xor_sync(0xffffffffu, t, o);
        if (tid == 0) s[0] = t;
    }
    __syncthreads();
    float r = s[0];
    __syncthreads();
    return r;
}

// ---------------- register-resident softmax for 512 cols ----------------
__global__ void softmax512_k(const float* __restrict__ x,
                             __nv_bfloat16* __restrict__ hi,
                             __nv_bfloat16* __restrict__ lo)
{
    size_t base = (size_t)blockIdx.x * 512;
    int tid = threadIdx.x;
    __shared__ float red[32];

    float v0 = x[base + tid];
    float v1 = x[base + tid + 256];

    float mx = fmaxf(v0, v1);
    #pragma unroll
    for (int o = 16; o; o >>= 1) mx = fmaxf(mx, __shfl_xor_sync(0xffffffffu, mx, o));
    if ((tid & 31) == 0) red[tid >> 5] = mx;
    __syncthreads();
    if (tid < 32) {
        float t = (tid < 8) ? red[tid] : -3.4e38f;
        #pragma unroll
        for (int o = 16; o; o >>= 1) t = fmaxf(t, __shfl_xor_sync(0xffffffffu, t, o));
        if (tid == 0) red[0] = t;
    }
    __syncthreads();
    mx = red[0];
    __syncthreads();

    float e0 = expf(v0 - mx);
    float e1 = expf(v1 - mx);
    float sum = blockReduceSum(e0 + e1, red);
    float inv = 1.f / sum;

    __nv_bfloat16 hh, ll;
    split1(e0 * inv, hh, ll);
    hi[base + tid] = hh; lo[base + tid] = ll;
    split1(e1 * inv, hh, ll);
    hi[base + tid + 256] = hh; lo[base + tid + 256] = ll;
}

// ---------------- fused x = LayerNorm(x + h) (+ split planes) ---------------
__global__ void add_ln_k(float* __restrict__ x, const float* __restrict__ h,
                         __nv_bfloat16* __restrict__ hi, __nv_bfloat16* __restrict__ lo,
                         const float* __restrict__ g, const float* __restrict__ b,
                         int ncols)
{
    size_t base = (size_t)blockIdx.x * ncols;
    int tid = threadIdx.x;
    __shared__ float red[32];

    float v[4];
    float sum = 0.f;
    int c = 0;
    for (int i = tid; i < ncols; i += blockDim.x, c++) {
        v[c] = x[base + i] + h[base + i];
        sum += v[c];
    }
    sum = blockReduceSum(sum, red);
    float mu = sum / ncols;

    float sq = 0.f;
    c = 0;
    for (int i = tid; i < ncols; i += blockDim.x, c++) {
        float d = v[c] - mu;
        sq += d * d;
    }
    sq = blockReduceSum(sq, red);
    float rstd = rsqrtf(sq / ncols + 1e-5f);

    c = 0;
    for (int i = tid; i < ncols; i += blockDim.x, c++) {
        float o = (v[c] - mu) * rstd * g[i] + b[i];
        x[base + i] = o;
        split1(o, hi[base + i], lo[base + i]);
    }
}

// ---------------- scheduled sampling mix (+ split planes) ----------------
__global__ void mix_k(float* __restrict__ x, const float* __restrict__ labels,
                      __nv_bfloat16* __restrict__ hi, __nv_bfloat16* __restrict__ lo,
                      const float* __restrict__ sr, const int* __restrict__ steps,
                      int total)
{
    int i = blockIdx.x * blockDim.x + threadIdx.x;
    if (i >= total) return;
    int s = (i / cE) % cS;
    int b = i / (cE * cS);
    float thr = (float)(*steps) / 200000.0f;
    float v = (sr[s * cB + b] >= thr) ? labels[i] : x[i];
    x[i] = v;
    split1(v, hi[i], lo[i]);
}

// ---------------- host dispatch ----------------
struct Planes { const __nv_bfloat16 *h, *l; };

static void launch_tmma(bool transB, bool relu, bool causal, bool causalA,
                        int M, int N, int K,
                        Planes A, int lda, long long sAo, long long sAi,
                        Planes B, int ldb, long long sBo, long long sBi,
                        float* C, __nv_bfloat16* Chi, __nv_bfloat16* Clo,
                        int ldc, long long sCo, long long sCi,
                        const float* bias, float scale, int nz, int innerH)
{
    dim3 blk(256);
    dim3 grd(N / 128, M / 128, nz);
    if (!transB) {
        if (causalA) {
            cudaFuncSetAttribute((const void*)tmma_k<false, false, false, true>,
                                 cudaFuncAttributeMaxDynamicSharedMemorySize, TSMEM);
            tmma_k<false, false, false, true><<<grd, blk, TSMEM>>>(K, A.h, A.l, lda, sAo, sAi,
                B.h, B.l, ldb, sBo, sBi, C, Chi, Clo, ldc, sCo, sCi, bias, scale, innerH);
        } else {
            cudaFuncSetAttribute((const void*)tmma_k<false, false, false, false>,
                                 cudaFuncAttributeMaxDynamicSharedMemorySize, TSMEM);
            tmma_k<false, false, false, false><<<grd, blk, TSMEM>>>(K, A.h, A.l, lda, sAo, sAi,
                B.h, B.l, ldb, sBo, sBi, C, Chi, Clo, ldc, sCo, sCi, bias, scale, innerH);
        }
    } else if (causal) {
        cudaFuncSetAttribute((const void*)tmma_k<true, false, true, false>,
                             cudaFuncAttributeMaxDynamicSharedMemorySize, TSMEM);
        tmma_k<true, false, true, false><<<grd, blk, TSMEM>>>(K, A.h, A.l, lda, sAo, sAi,
            B.h, B.l, ldb, sBo, sBi, C, Chi, Clo, ldc, sCo, sCi, bias, scale, innerH);
    } else if (relu) {
        cudaFuncSetAttribute((const void*)tmma_k<true, true, false, false>,
                             cudaFuncAttributeMaxDynamicSharedMemorySize, TSMEM);
        tmma_k<true, true, false, false><<<grd, blk, TSMEM>>>(K, A.h, A.l, lda, sAo, sAi,
            B.h, B.l, ldb, sBo, sBi, C, Chi, Clo, ldc, sCo, sCi, bias, scale, innerH);
    } else {
        cudaFuncSetAttribute((const void*)tmma_k<true, false, false, false>,
                             cudaFuncAttributeMaxDynamicSharedMemorySize, TSMEM);
        tmma_k<true, false, false, false><<<grd, blk, TSMEM>>>(K, A.h, A.l, lda, sAo, sAi,
            B.h, B.l, ldb, sBo, sBi, C, Chi, Clo, ldc, sCo, sCi, bias, scale, innerH);
    }
}

template<typename T>
static T* sym(T* symbol) {
    void* p = nullptr;
    cudaGetSymbolAddress(&p, (const void*)symbol);
    return (T*)p;
}

extern "C" void kernel_launch(void* const* d_in, const int* in_sizes, int n_in,
                              void* d_out, int out_size)
{
    const float* batch    = (const float*)d_in[0];
    const float* labels   = (const float*)d_in[1];
    const float* sched    = (const float*)d_in[2];
    const int*   steps    = (const int*)  d_in[3];
    const float* W_pre    = (const float*)d_in[4];
    const float* b_pre    = (const float*)d_in[5];
    const float* W_enc    = (const float*)d_in[6];
    const float* b_enc    = (const float*)d_in[7];
    const float* W_e2d    = (const float*)d_in[8];
    const float* b_e2d    = (const float*)d_in[9];
    const float* sa_in_w  = (const float*)d_in[10];
    const float* sa_in_b  = (const float*)d_in[11];
    const float* sa_out_w = (const float*)d_in[12];
    const float* sa_out_b = (const float*)d_in[13];
    const float* ca_in_w  = (const float*)d_in[14];
    const float* ca_in_b  = (const float*)d_in[15];
    const float* ca_out_w = (const float*)d_in[16];
    const float* ca_out_b = (const float*)d_in[17];
    const float* w1       = (const float*)d_in[18];
    const float* b1       = (const float*)d_in[19];
    const float* w2       = (const float*)d_in[20];
    const float* b2       = (const float*)d_in[21];
    const float* g1       = (const float*)d_in[22];
    const float* be1      = (const float*)d_in[23];
    const float* g2       = (const float*)d_in[24];
    const float* be2      = (const float*)d_in[25];
    const float* g3       = (const float*)d_in[26];
    const float* be3      = (const float*)d_in[27];

    float* x  = sym(g_x);
    float* h  = sym(g_h);
    float* sc = sym(g_sc);

    __nv_bfloat16 *xh = sym(x_h), *xl = sym(x_l);
    __nv_bfloat16 *ah = sym(a_h), *al = sym(a_l);
    __nv_bfloat16 *memh = sym(mem_h), *meml = sym(mem_l);
    __nv_bfloat16 *ench = sym(enc_h), *encl = sym(enc_l);
    __nv_bfloat16 *qkvh = sym(qkv_h), *qkvl = sym(qkv_l);
    __nv_bfloat16 *sch = sym(sc_h), *scl = sym(sc_l);
    __nv_bfloat16 *cakvh = sym(cakv_h), *cakvl = sym(cakv_l);
    __nv_bfloat16 *wsaih = sym(wsai_h), *wsail = sym(wsai_l);
    __nv_bfloat16 *wsaoh = sym(wsao_h), *wsaol = sym(wsao_l);
    __nv_bfloat16 *wcaih = sym(wcai_h), *wcail = sym(wcai_l);
    __nv_bfloat16 *wcaoh = sym(wcao_h), *wcaol = sym(wcao_l);
    __nv_bfloat16 *ww1h = sym(ww1_h), *ww1l = sym(ww1_l);
    __nv_bfloat16 *ww2h = sym(ww2_h), *ww2l = sym(ww2_l);
    __nv_bfloat16 *wench = sym(wenc_h), *wencl = sym(wenc_l);
    __nv_bfloat16 *we2dh = sym(we2d_h), *we2dl = sym(we2d_l);

    const float atscale = 1.0f / sqrtf((float)cHD);
    const long long sQb  = (long long)cS * 3 * cE;
    const long long sKVb = (long long)cS * 2 * cE;
    const long long sScb = (long long)cH * cS * cS;
    const long long sSch = (long long)cS * cS;
    const long long sAb  = (long long)cS * cE;

    // ---- weight splits (once per call) ----
    auto spl = [](const float* s, __nv_bfloat16* hh, __nv_bfloat16* ll, int n) {
        split_k<<<(n + 255) / 256, 256>>>(s, hh, ll, n);
    };
    spl(sa_in_w,  wsaih, wsail, cL * 3 * cE * cE);
    spl(sa_out_w, wsaoh, wsaol, cL * cE * cE);
    spl(ca_in_w,  wcaih, wcail, cL * 3 * cE * cE);
    spl(ca_out_w, wcaoh, wcaol, cL * cE * cE);
    spl(w1, ww1h, ww1l, cL * cFF * cE);
    spl(w2, ww2h, ww2l, cL * cE * cFF);
    spl(W_enc, wench, wencl, cE * cENC);
    spl(W_e2d, we2dh, we2dl, cENC * cE);

    // ---- prenet (SIMT, K=234, planes only) + encoder chain (NN tensor) ----
    {
        dim3 blk(256), grd(cE / BN, cM / BM, 1);
        gemm_nn_k<<<grd, blk>>>(cM, cE, cIN, batch, cIN, W_pre, cE,
                                ah, al, cE, b_pre);
    }
    launch_tmma(false, false, false, false, cM, cENC, cE,
                {ah, al}, cE, 0, 0, {wench, wencl}, cENC, 0, 0,
                nullptr, ench, encl, cENC, 0, 0, b_enc, 1.f, 1, 1);
    launch_tmma(false, false, false, false, cM, cE, cENC,
                {ench, encl}, cENC, 0, 0, {we2dh, we2dl}, cE, 0, 0,
                nullptr, memh, meml, cE, 0, 0, b_e2d, 1.f, 1, 1);

    {
        int total = cM * cE;
        copy_split_k<<<(total + 255) / 256, 256>>>(x, labels, xh, xl, total);
    }

    for (int p = 0; p < 2; p++) {
        for (int l = 0; l < cL; l++) {
            size_t wqkvOff = (size_t)l * 3 * cE * cE;
            size_t woOff   = (size_t)l * cE * cE;
            const float* sib = sa_in_b + (size_t)l * 3 * cE;
            const float* cib = ca_in_b + (size_t)l * 3 * cE;
            size_t kvOff = (size_t)l * cM * 2 * cE;

            // ===== self-attention =====
            launch_tmma(true, false, false, false, cM, 3 * cE, cE,
                        {xh, xl}, cE, 0, 0,
                        {wsaih + wqkvOff, wsail + wqkvOff}, cE, 0, 0,
                        nullptr, qkvh, qkvl, 3 * cE, 0, 0, sib, 1.f, 1, 1);
            launch_tmma(true, false, true, false, cS, cS, cHD,
                        {qkvh, qkvl}, 3 * cE, sQb, cHD,
                        {qkvh + cE, qkvl + cE}, 3 * cE, sQb, cHD,
                        sc, nullptr, nullptr, cS, sScb, sSch, nullptr, atscale,
                        cB * cH, cH);
            softmax512_k<<<cB * cH * cS, 256>>>(sc, sch, scl);
            // attn*V with causal-A K-trim (P rows are exactly 0 past diagonal)
            launch_tmma(false, false, false, true, cS, cHD, cS,
                        {sch, scl}, cS, sScb, sSch,
                        {qkvh + 2 * cE, qkvl + 2 * cE}, 3 * cE, sQb, cHD,
                        nullptr, ah, al, cE, sAb, cHD, nullptr, 1.f, cB * cH, cH);
            launch_tmma(true, false, false, false, cM, cE, cE,
                        {ah, al}, cE, 0, 0,
                        {wsaoh + woOff, wsaol + woOff}, cE, 0, 0,
                        h, nullptr, nullptr, cE, 0, 0,
                        sa_out_b + (size_t)l * cE, 1.f, 1, 1);
            add_ln_k<<<cM, 256>>>(x, h, xh, xl,
                                  g1 + (size_t)l * cE, be1 + (size_t)l * cE, cE);

            // ===== cross-attention (K/V cached across passes) =====
            launch_tmma(true, false, false, false, cM, cE, cE,
                        {xh, xl}, cE, 0, 0,
                        {wcaih + wqkvOff, wcail + wqkvOff}, cE, 0, 0,
                        nullptr, qkvh, qkvl, 3 * cE, 0, 0, cib, 1.f, 1, 1);
            if (p == 0)
                launch_tmma(true, false, false, false, cM, 2 * cE, cE,
                            {memh, meml}, cE, 0, 0,
                            {wcaih + wqkvOff + (size_t)cE * cE,
                             wcail + wqkvOff + (size_t)cE * cE}, cE, 0, 0,
                            nullptr, cakvh + kvOff, cakvl + kvOff,
                            2 * cE, 0, 0, cib + cE, 1.f, 1, 1);
            launch_tmma(true, false, false, false, cS, cS, cHD,
                        {qkvh, qkvl}, 3 * cE, sQb, cHD,
                        {cakvh + kvOff, cakvl + kvOff}, 2 * cE, sKVb, cHD,
                        sc, nullptr, nullptr, cS, sScb, sSch, nullptr, atscale,
                        cB * cH, cH);
            softmax512_k<<<cB * cH * cS, 256>>>(sc, sch, scl);
            launch_tmma(false, false, false, false, cS, cHD, cS,
                        {sch, scl}, cS, sScb, sSch,
                        {cakvh + kvOff + cE, cakvl + kvOff + cE}, 2 * cE, sKVb, cHD,
                        nullptr, ah, al, cE, sAb, cHD, nullptr, 1.f, cB * cH, cH);
            launch_tmma(true, false, false, false, cM, cE, cE,
                        {ah, al}, cE, 0, 0,
                        {wcaoh + woOff, wcaol + woOff}, cE, 0, 0,
                        h, nullptr, nullptr, cE, 0, 0,
                        ca_out_b + (size_t)l * cE, 1.f, 1, 1);
            add_ln_k<<<cM, 256>>>(x, h, xh, xl,
                                  g2 + (size_t)l * cE, be2 + (size_t)l * cE, cE);

            // ===== FFN (relu) — hidden planes reuse qkv plane buffers =====
            launch_tmma(true, true, false, false, cM, cFF, cE,
                        {xh, xl}, cE, 0, 0,
                        {ww1h + (size_t)l * cFF * cE, ww1l + (size_t)l * cFF * cE},
                        cE, 0, 0,
                        nullptr, qkvh, qkvl, cFF, 0, 0, b1 + (size_t)l * cFF, 1.f, 1, 1);
            launch_tmma(true, false, false, false, cM, cE, cFF,
                        {qkvh, qkvl}, cFF, 0, 0,
                        {ww2h + (size_t)l * cE * cFF, ww2l + (size_t)l * cE * cFF},
                        cFF, 0, 0,
                        h, nullptr, nullptr, cE, 0, 0, b2 + (size_t)l * cE, 1.f, 1, 1);
            add_ln_k<<<cM, 256>>>(x, h, xh, xl,
                                  g3 + (size_t)l * cE, be3 + (size_t)l * cE, cE);
        }
        if (p == 0) {
            int total = cM * cE;
            mix_k<<<(total + 255) / 256, 256>>>(x, labels, xh, xl, sched, steps, total);
        }
    }

    cudaMemcpyAsync(d_out, x, sizeof(float) * (size_t)cM * cE,
                    cudaMemcpyDeviceToDevice);
}